// round 4
// baseline (speedup 1.0000x reference)
#include <cuda_runtime.h>
#include <math.h>

#define NN   32768
#define FF   64
#define HH   4
#define HF   256
#define ESZ  524288
#define EGZ  524288
#define GG   64
#define NCLS 10
#define BNEPS 1e-5f

// ---------------- device scratch (static allocation only) ----------------
__device__ float    d_xs[4][NN*FF];     // x0..x3 (GAT inputs)
__device__ float    d_xh[3][NN*FF];     // xh1..xh3 intermediates
__device__ float    d_h[NN*HF];         // h = x @ W   [N,256]
__device__ float    d_as[NN*HH];
__device__ float    d_ad[NN*HH];
__device__ unsigned d_mmax[NN*HH];      // ordered-uint float max
__device__ float    d_denom[NN*HH];
__device__ float    d_gacc[NN*HF];      // attention accumulation, then elu(gat)
__device__ float    d_z[NN*FF];         // mlp output
__device__ float    d_acc[NN*FF];       // running residual x + sum(bn_out)
__device__ float    d_bnmu[FF];
__device__ float    d_bnrstd[FF];
__device__ float    d_pooled[GG*FF];
__device__ float    d_h1[GG*256];
__device__ float    d_h2[GG*128];

// ---------------- helpers ----------------
__device__ __forceinline__ unsigned f2ord(float f) {
    unsigned u = __float_as_uint(f);
    return (u & 0x80000000u) ? ~u : (u | 0x80000000u);
}
__device__ __forceinline__ float ord2f(unsigned u) {
    return (u & 0x80000000u) ? __uint_as_float(u & 0x7fffffffu) : __uint_as_float(~u);
}
__device__ __forceinline__ float lrelu(float x) { return x >= 0.f ? x : 0.2f * x; }
__device__ __forceinline__ float elu(float x)   { return x > 0.f ? x : expm1f(x); }

// ---------------- generic kernels ----------------
__global__ void zero_kernel(float4* p, int n4) {
    int i = blockIdx.x * blockDim.x + threadIdx.x;
    if (i < n4) p[i] = make_float4(0.f, 0.f, 0.f, 0.f);
}

__global__ void copy_kernel(const float4* __restrict__ in, float4* __restrict__ out, int n4) {
    int i = blockIdx.x * blockDim.x + threadIdx.x;
    if (i < n4) out[i] = in[i];
}

__global__ void abs_kernel(float* p, int n) {
    int i = blockIdx.x * blockDim.x + threadIdx.x;
    if (i < n) p[i] = fabsf(p[i]);
}

// scatter-add: out[dst] += attr[e] * in[src], rows of 64 floats; warp per edge
__global__ void scatter_kernel(const int* __restrict__ src, const int* __restrict__ dst,
                               const float* __restrict__ attr, const float* __restrict__ in,
                               float* __restrict__ out, int E) {
    int warp = (blockIdx.x * blockDim.x + threadIdx.x) >> 5;
    int lane = threadIdx.x & 31;
    if (warp >= E) return;
    int s = src[warp], d = dst[warp];
    float a = attr[warp];
    const float* ip = in + (size_t)s * FF;
    float* op = out + (size_t)d * FF;
    atomicAdd(op + lane,      a * ip[lane]);
    atomicAdd(op + lane + 32, a * ip[lane + 32]);
}

// generic fp32 GEMM: C[M,Nc] = A[M,K] @ B[K,Nc] (+bias). BM=BN=64, BK=16, 4x4/thread.
__global__ void gemm_kernel(const float* __restrict__ A, const float* __restrict__ B,
                            const float* __restrict__ bias, float* __restrict__ C,
                            int M, int Nc, int K) {
    __shared__ float As[16][68];
    __shared__ float Bs[16][68];
    int tid = threadIdx.x;
    int tx = tid & 15, ty = tid >> 4;
    int nb = Nc >> 6;
    int bn = (blockIdx.x % nb) * 64;
    int bm = (blockIdx.x / nb) * 64;
    float acc[4][4] = {};
    for (int k0 = 0; k0 < K; k0 += 16) {
        {
            int m = tid >> 2;
            int kk = (tid & 3) * 4;
            float4 v = *(const float4*)(A + (size_t)(bm + m) * K + k0 + kk);
            As[kk + 0][m] = v.x; As[kk + 1][m] = v.y; As[kk + 2][m] = v.z; As[kk + 3][m] = v.w;
        }
        {
            int kk = tid >> 4;
            int n = (tid & 15) * 4;
            *(float4*)&Bs[kk][n] = *(const float4*)(B + (size_t)(k0 + kk) * Nc + bn + n);
        }
        __syncthreads();
#pragma unroll
        for (int kk = 0; kk < 16; kk++) {
            float4 a = *(float4*)&As[kk][ty * 4];
            float4 b = *(float4*)&Bs[kk][tx * 4];
            acc[0][0] += a.x * b.x; acc[0][1] += a.x * b.y; acc[0][2] += a.x * b.z; acc[0][3] += a.x * b.w;
            acc[1][0] += a.y * b.x; acc[1][1] += a.y * b.y; acc[1][2] += a.y * b.z; acc[1][3] += a.y * b.w;
            acc[2][0] += a.z * b.x; acc[2][1] += a.z * b.y; acc[2][2] += a.z * b.z; acc[2][3] += a.z * b.w;
            acc[3][0] += a.w * b.x; acc[3][1] += a.w * b.y; acc[3][2] += a.w * b.z; acc[3][3] += a.w * b.w;
        }
        __syncthreads();
    }
#pragma unroll
    for (int i = 0; i < 4; i++) {
#pragma unroll
        for (int j = 0; j < 4; j++) {
            float v = acc[i][j];
            if (bias) v += bias[bn + tx * 4 + j];
            C[(size_t)(bm + ty * 4 + i) * Nc + bn + tx * 4 + j] = v;
        }
    }
}

// a_s[n,h] = <h[n,h,:], asrc[h,:]>, a_d likewise. warp per (n,h).
__global__ void asad_kernel(const float* __restrict__ h, const float* __restrict__ asrc,
                            const float* __restrict__ adst, float* __restrict__ a_s,
                            float* __restrict__ a_d) {
    int warp = (blockIdx.x * blockDim.x + threadIdx.x) >> 5;
    int lane = threadIdx.x & 31;
    if (warp >= NN * HH) return;
    int n = warp >> 2, hh = warp & 3;
    float2 hv = *(const float2*)(h + (size_t)n * HF + hh * FF + lane * 2);
    float2 ws = *(const float2*)(asrc + hh * FF + lane * 2);
    float2 wd = *(const float2*)(adst + hh * FF + lane * 2);
    float ss = hv.x * ws.x + hv.y * ws.y;
    float dd = hv.x * wd.x + hv.y * wd.y;
    for (int o = 16; o; o >>= 1) {
        ss += __shfl_down_sync(0xffffffffu, ss, o);
        dd += __shfl_down_sync(0xffffffffu, dd, o);
    }
    if (lane == 0) { a_s[warp] = ss; a_d[warp] = dd; }
}

// pass 1: segment max of leaky_relu(a_s[src]+a_d[dst]) at dst. thread per edge.
__global__ void attmax_kernel(const int* __restrict__ src, const int* __restrict__ dst,
                              const float* __restrict__ a_s, const float* __restrict__ a_d,
                              unsigned* __restrict__ mmax) {
    int e = blockIdx.x * blockDim.x + threadIdx.x;
    if (e >= EGZ + NN) return;
    int s, d;
    if (e < EGZ) { s = src[e]; d = dst[e]; } else { s = d = e - EGZ; }
    float4 s4 = *(const float4*)(a_s + (size_t)s * 4);
    float4 d4 = *(const float4*)(a_d + (size_t)d * 4);
    atomicMax(&mmax[d * 4 + 0], f2ord(lrelu(s4.x + d4.x)));
    atomicMax(&mmax[d * 4 + 1], f2ord(lrelu(s4.y + d4.y)));
    atomicMax(&mmax[d * 4 + 2], f2ord(lrelu(s4.z + d4.z)));
    atomicMax(&mmax[d * 4 + 3], f2ord(lrelu(s4.w + d4.w)));
}

// pass 2: denom[dst] += ex ;  gacc[dst] += ex * h[src]. warp per edge, contiguous REDs.
__global__ void attacc_kernel(const int* __restrict__ src, const int* __restrict__ dst,
                              const float* __restrict__ a_s, const float* __restrict__ a_d,
                              const unsigned* __restrict__ mmax, const float* __restrict__ h,
                              float* __restrict__ denom, float* __restrict__ gacc) {
    int warp = (blockIdx.x * blockDim.x + threadIdx.x) >> 5;
    int lane = threadIdx.x & 31;
    if (warp >= EGZ + NN) return;
    int s, d;
    if (warp < EGZ) { s = src[warp]; d = dst[warp]; } else { s = d = warp - EGZ; }
    float4 s4 = *(const float4*)(a_s + (size_t)s * 4);
    float4 d4 = *(const float4*)(a_d + (size_t)d * 4);
    float ex[4];
    ex[0] = expf(lrelu(s4.x + d4.x) - ord2f(mmax[d * 4 + 0]));
    ex[1] = expf(lrelu(s4.y + d4.y) - ord2f(mmax[d * 4 + 1]));
    ex[2] = expf(lrelu(s4.z + d4.z) - ord2f(mmax[d * 4 + 2]));
    ex[3] = expf(lrelu(s4.w + d4.w) - ord2f(mmax[d * 4 + 3]));
    if (lane < 4) atomicAdd(&denom[d * 4 + lane], ex[lane]);
    const float* hp = h + (size_t)s * HF;
    float* gp = gacc + (size_t)d * HF;
#pragma unroll
    for (int j = 0; j < 8; j++) {
        float v = hp[j * 32 + lane];
        atomicAdd(gp + j * 32 + lane, ex[j >> 1] * v);
    }
}

// finalize: gacc = elu(gacc/denom + bias)
__global__ void gatfin_kernel(float* __restrict__ gacc, const float* __restrict__ denom,
                              const float* __restrict__ gb) {
    int idx = blockIdx.x * blockDim.x + threadIdx.x;
    if (idx >= NN * HF) return;
    int n = idx >> 8, c = idx & 255;
    float v = gacc[idx] / denom[n * 4 + (c >> 6)] + gb[c];
    gacc[idx] = elu(v);
}

// BN stats: one block per feature column, block-reduce in double, no atomics.
__global__ void bnstats_kernel(const float* __restrict__ z,
                               float* __restrict__ mu_out, float* __restrict__ rstd_out) {
    int f = blockIdx.x;            // 0..63
    int t = threadIdx.x;           // 256 threads
    double s = 0.0, q = 0.0;
    for (int r = t; r < NN; r += 256) {
        float v = z[(size_t)r * FF + f];
        s += v; q += (double)v * v;
    }
    __shared__ double sh_s[256];
    __shared__ double sh_q[256];
    sh_s[t] = s; sh_q[t] = q;
    __syncthreads();
    for (int o = 128; o > 0; o >>= 1) {
        if (t < o) { sh_s[t] += sh_s[t + o]; sh_q[t] += sh_q[t + o]; }
        __syncthreads();
    }
    if (t == 0) {
        double mu = sh_s[0] / NN;
        double var = sh_q[0] / NN - mu * mu;
        mu_out[f] = (float)mu;
        rstd_out[f] = rsqrtf((float)var + BNEPS);
    }
}

// apply BN and accumulate into residual
__global__ void bnapply_kernel(const float* __restrict__ z, const float* __restrict__ g,
                               const float* __restrict__ beta, float* __restrict__ acc,
                               const float* __restrict__ mu, const float* __restrict__ rstd) {
    int idx = blockIdx.x * blockDim.x + threadIdx.x;
    if (idx >= NN * FF) return;
    int f = idx & 63;
    float o = (z[idx] - mu[f]) * rstd[f] * g[f] + beta[f];
    acc[idx] += o;
}

// global add pool
__global__ void pool_kernel(const float* __restrict__ acc, const int* __restrict__ batch,
                            float* __restrict__ pooled) {
    int idx = blockIdx.x * blockDim.x + threadIdx.x;
    if (idx >= NN * FF) return;
    int n = idx >> 6, f = idx & 63;
    atomicAdd(&pooled[batch[n] * FF + f], acc[idx]);
}

// tiny FC + BN (+relu): one block per output column, 64 threads = 64 graph rows
__global__ void fcbn_kernel(const float* __restrict__ A, const float* __restrict__ W,
                            const float* __restrict__ b, const float* __restrict__ g,
                            const float* __restrict__ beta, float* __restrict__ out,
                            int K, int Nc, int do_relu) {
    int j = blockIdx.x;
    int r = threadIdx.x;
    float y = b[j];
    for (int k = 0; k < K; k++) y += A[r * K + k] * W[k * Nc + j];
    __shared__ float sh[GG];
    __shared__ float s_mu, s_var;
    sh[r] = y;
    __syncthreads();
    if (r == 0) {
        float s = 0.f;
        for (int i = 0; i < GG; i++) s += sh[i];
        float mu = s / GG;
        float q = 0.f;
        for (int i = 0; i < GG; i++) { float dd = sh[i] - mu; q += dd * dd; }
        s_mu = mu; s_var = q / GG;
    }
    __syncthreads();
    float o = (y - s_mu) * rsqrtf(s_var + BNEPS) * g[j] + beta[j];
    if (do_relu) o = fmaxf(o, 0.f);
    out[r * Nc + j] = o;
}

// ---------------- launch ----------------
static inline void* sym(const void* s) {
    void* p = nullptr;
    cudaGetSymbolAddress(&p, s);
    return p;
}

extern "C" void kernel_launch(void* const* d_in, const int* in_sizes, int n_in,
                              void* d_out, int out_size) {
    const float* x       = (const float*)d_in[0];
    const int*  eidx     = (const int*)d_in[1];
    const int*  batch    = (const int*)d_in[2];
    const int*  sidx     = (const int*)d_in[3];
    const float* sattr   = (const float*)d_in[4];
    const float* gat_W   = (const float*)d_in[5];
    const float* gat_as  = (const float*)d_in[6];
    const float* gat_ad  = (const float*)d_in[7];
    const float* gat_b   = (const float*)d_in[8];
    const float* mlp_W   = (const float*)d_in[9];
    const float* mlp_b   = (const float*)d_in[10];
    const float* mlp_g   = (const float*)d_in[11];
    const float* mlp_be  = (const float*)d_in[12];
    const float* fc1_W   = (const float*)d_in[13];
    const float* fc1_b   = (const float*)d_in[14];
    const float* fc1_g   = (const float*)d_in[15];
    const float* fc1_be  = (const float*)d_in[16];
    const float* fc2_W   = (const float*)d_in[17];
    const float* fc2_b   = (const float*)d_in[18];
    const float* fc2_g   = (const float*)d_in[19];
    const float* fc2_be  = (const float*)d_in[20];
    const float* fc3_W   = (const float*)d_in[21];
    const float* fc3_b   = (const float*)d_in[22];
    const float* fc3_g   = (const float*)d_in[23];
    const float* fc3_be  = (const float*)d_in[24];
    float* out = (float*)d_out;

    float*    p_xs     = (float*)sym(d_xs);
    float*    p_xh     = (float*)sym(d_xh);
    float*    p_h      = (float*)sym(d_h);
    float*    p_as     = (float*)sym(d_as);
    float*    p_ad     = (float*)sym(d_ad);
    unsigned* p_mmax   = (unsigned*)sym(d_mmax);
    float*    p_denom  = (float*)sym(d_denom);
    float*    p_gacc   = (float*)sym(d_gacc);
    float*    p_z      = (float*)sym(d_z);
    float*    p_acc    = (float*)sym(d_acc);
    float*    p_bnmu   = (float*)sym(d_bnmu);
    float*    p_bnrstd = (float*)sym(d_bnrstd);
    float*    p_pooled = (float*)sym(d_pooled);
    float*    p_h1     = (float*)sym(d_h1);
    float*    p_h2     = (float*)sym(d_h2);

    const int TB = 256;
    const int EW = ((ESZ * 32) + TB - 1) / TB;          // warp-per-edge scatter
    const int E2 = EGZ + NN;
    const int E2T = (E2 + TB - 1) / TB;
    const int E2W = ((E2 * 32) + TB - 1) / TB;

    // ---- zero accumulators ----
    {
        int n4 = 4 * NN * FF / 4;
        zero_kernel<<<(n4 + TB - 1) / TB, TB>>>((float4*)p_xs, n4);
        n4 = 3 * NN * FF / 4;
        zero_kernel<<<(n4 + TB - 1) / TB, TB>>>((float4*)p_xh, n4);
    }

    // ---- solo passes ----
    const int* s0 = sidx + 0 * 2 * ESZ;
    scatter_kernel<<<EW, TB>>>(s0, s0 + ESZ, sattr + 0 * ESZ, x, p_xs + 0 * NN * FF, ESZ);
    for (int k = 1; k < 4; k++) {
        const int* sk = sidx + k * 2 * ESZ;
        scatter_kernel<<<EW, TB>>>(sk, sk + ESZ, sattr + k * ESZ, x, p_xh + (k - 1) * NN * FF, ESZ);
    }
    abs_kernel<<<(3 * NN * FF + TB - 1) / TB, TB>>>(p_xh, 3 * NN * FF);
    for (int k = 1; k < 4; k++) {
        scatter_kernel<<<EW, TB>>>(s0, s0 + ESZ, sattr + 0 * ESZ,
                                   p_xh + (k - 1) * NN * FF, p_xs + k * NN * FF, ESZ);
    }

    // ---- residual accumulator = x ----
    copy_kernel<<<(NN * FF / 4 + TB - 1) / TB, TB>>>((const float4*)x, (float4*)p_acc, NN * FF / 4);

    // ---- 4 GAT + MLP + BN layers ----
    for (int i = 0; i < 4; i++) {
        // h = xs[i] @ gat_W[i]   [N,64]@[64,256]
        gemm_kernel<<<(NN / 64) * (HF / 64), TB>>>(p_xs + i * NN * FF, gat_W + i * FF * HF,
                                                   nullptr, p_h, NN, HF, FF);
        asad_kernel<<<(NN * HH * 32 + TB - 1) / TB, TB>>>(p_h, gat_as + i * HH * FF,
                                                          gat_ad + i * HH * FF, p_as, p_ad);
        {
            int n4 = NN * HH / 4;
            zero_kernel<<<(n4 + TB - 1) / TB, TB>>>((float4*)p_mmax, n4);
            zero_kernel<<<(n4 + TB - 1) / TB, TB>>>((float4*)p_denom, n4);
            n4 = NN * HF / 4;
            zero_kernel<<<(n4 + TB - 1) / TB, TB>>>((float4*)p_gacc, n4);
        }
        attmax_kernel<<<E2T, TB>>>(eidx, eidx + EGZ, p_as, p_ad, p_mmax);
        attacc_kernel<<<E2W, TB>>>(eidx, eidx + EGZ, p_as, p_ad, p_mmax, p_h, p_denom, p_gacc);
        gatfin_kernel<<<(NN * HF + TB - 1) / TB, TB>>>(p_gacc, p_denom, gat_b + i * HF);
        // z = elu(gat) @ mlp_W[i] + mlp_b[i]   [N,256]@[256,64]
        gemm_kernel<<<(NN / 64) * (FF / 64), TB>>>(p_gacc, mlp_W + i * HF * FF,
                                                   mlp_b + i * FF, p_z, NN, FF, HF);
        bnstats_kernel<<<FF, 256>>>(p_z, p_bnmu, p_bnrstd);
        bnapply_kernel<<<(NN * FF + TB - 1) / TB, TB>>>(p_z, mlp_g + i * FF, mlp_be + i * FF,
                                                        p_acc, p_bnmu, p_bnrstd);
    }

    // ---- pooling + FC head ----
    zero_kernel<<<(GG * FF / 4 + TB - 1) / TB, TB>>>((float4*)p_pooled, GG * FF / 4);
    pool_kernel<<<(NN * FF + TB - 1) / TB, TB>>>(p_acc, batch, p_pooled);
    fcbn_kernel<<<256, GG>>>(p_pooled, fc1_W, fc1_b, fc1_g, fc1_be, p_h1, 64, 256, 1);
    fcbn_kernel<<<128, GG>>>(p_h1, fc2_W, fc2_b, fc2_g, fc2_be, p_h2, 256, 128, 1);
    fcbn_kernel<<<NCLS, GG>>>(p_h2, fc3_W, fc3_b, fc3_g, fc3_be, out, 128, NCLS, 0);
}

// round 5
// speedup vs baseline: 1.3133x; 1.3133x over previous
#include <cuda_runtime.h>
#include <math.h>

#define NN   32768
#define FF   64
#define HH   4
#define HF   256
#define ESZ  524288
#define EGZ  524288
#define GG   64
#define NCLS 10
#define BNEPS 1e-5f

// ---------------- device scratch (static allocation only) ----------------
__device__ float  d_xs[4][NN*FF];     // x0..x3 (GAT inputs)
__device__ float  d_xh[3][NN*FF];     // xh1..xh3 intermediates
__device__ float  d_h[NN*HF];         // h = x @ W   [N,256]
__device__ float  d_as[NN*HH];
__device__ float  d_ad[NN*HH];
__device__ float  d_gacc[NN*HF];      // elu(gat output)
__device__ float  d_z[NN*FF];         // mlp output
__device__ float  d_acc[NN*FF];       // running residual x + sum(bn_out)
__device__ double d_bnpart[256*FF*2]; // stage-1 BN partials (sum, sumsq)
__device__ float  d_bnmu[FF];
__device__ float  d_bnrstd[FF];
__device__ float  d_pooled[GG*FF];
__device__ float  d_h1[GG*256];
__device__ float  d_h2[GG*128];
// CSR scratch: ids 0..3 = scatter graphs, 4 = gat edge graph
__device__ int    d_cnt[2*NN];        // [0,NN)=hist count, [NN,2NN)=fill cursor
__device__ int    d_rowptr[5][NN+1];
__device__ int    d_csrc[5][ESZ];
__device__ float  d_cattr[4][ESZ];

// ---------------- helpers ----------------
__device__ __forceinline__ float lrelu(float x) { return x >= 0.f ? x : 0.2f * x; }
__device__ __forceinline__ float elu(float x)   { return x > 0.f ? x : expm1f(x); }

__global__ void zero_i_kernel(int* p, int n) {
    int i = blockIdx.x * blockDim.x + threadIdx.x;
    if (i < n) p[i] = 0;
}
__global__ void zero_f_kernel(float4* p, int n4) {
    int i = blockIdx.x * blockDim.x + threadIdx.x;
    if (i < n4) p[i] = make_float4(0.f, 0.f, 0.f, 0.f);
}
__global__ void copy_kernel(const float4* __restrict__ in, float4* __restrict__ out, int n4) {
    int i = blockIdx.x * blockDim.x + threadIdx.x;
    if (i < n4) out[i] = in[i];
}

// ---------------- CSR build ----------------
__global__ void hist_kernel(const int* __restrict__ dst, int* __restrict__ cnt, int E) {
    int e = blockIdx.x * blockDim.x + threadIdx.x;
    if (e < E) atomicAdd(&cnt[dst[e]], 1);
}

// exclusive scan over NN=32768 counts; single block of 1024 threads, 32/thread
__global__ void scan_kernel(const int* __restrict__ cnt, int* __restrict__ rowptr) {
    __shared__ int sh[1024];
    int t = threadIdx.x;
    int base = t * 32;
    int local[32];
    int s = 0;
#pragma unroll
    for (int i = 0; i < 32; i++) { local[i] = s; s += cnt[base + i]; }
    sh[t] = s;
    __syncthreads();
    for (int o = 1; o < 1024; o <<= 1) {
        int v = (t >= o) ? sh[t - o] : 0;
        __syncthreads();
        sh[t] += v;
        __syncthreads();
    }
    int off = (t == 0) ? 0 : sh[t - 1];
#pragma unroll
    for (int i = 0; i < 32; i++) rowptr[base + i] = off + local[i];
    if (t == 1023) rowptr[NN] = sh[1023];
}

__global__ void fill_kernel(const int* __restrict__ src, const int* __restrict__ dst,
                            const float* __restrict__ attr, const int* __restrict__ rowptr,
                            int* __restrict__ cursor, int* __restrict__ csrc,
                            float* __restrict__ cattr, int E) {
    int e = blockIdx.x * blockDim.x + threadIdx.x;
    if (e >= E) return;
    int d = dst[e];
    int pos = rowptr[d] + atomicAdd(&cursor[d], 1);
    csrc[pos] = src[e];
    if (cattr) cattr[pos] = attr[e];
}

// ---------------- CSR gathers (warp per node) ----------------
// out[d,:] = (abs?) sum_e attr_e * in[src_e,:]
__global__ void gather1_kernel(const int* __restrict__ rowptr, const int* __restrict__ csrc,
                               const float* __restrict__ cattr, const float* __restrict__ in,
                               float* __restrict__ out, int do_abs) {
    int warp = (blockIdx.x * blockDim.x + threadIdx.x) >> 5;
    int lane = threadIdx.x & 31;
    if (warp >= NN) return;
    int beg = rowptr[warp], end = rowptr[warp + 1];
    float a0 = 0.f, a1 = 0.f;
    for (int e = beg; e < end; e++) {
        int s = csrc[e];
        float a = cattr[e];
        const float* ip = in + (size_t)s * FF;
        a0 += a * ip[lane];
        a1 += a * ip[32 + lane];
    }
    if (do_abs) { a0 = fabsf(a0); a1 = fabsf(a1); }
    float* op = out + (size_t)warp * FF;
    op[lane] = a0;
    op[32 + lane] = a1;
}

// three inputs through the same CSR: out_k[d,:] = sum_e attr_e * in_k[src_e,:]
__global__ void gather3_kernel(const int* __restrict__ rowptr, const int* __restrict__ csrc,
                               const float* __restrict__ cattr,
                               const float* __restrict__ in0, const float* __restrict__ in1,
                               const float* __restrict__ in2,
                               float* __restrict__ o0, float* __restrict__ o1,
                               float* __restrict__ o2) {
    int warp = (blockIdx.x * blockDim.x + threadIdx.x) >> 5;
    int lane = threadIdx.x & 31;
    if (warp >= NN) return;
    int beg = rowptr[warp], end = rowptr[warp + 1];
    float a00 = 0.f, a01 = 0.f, a10 = 0.f, a11 = 0.f, a20 = 0.f, a21 = 0.f;
    for (int e = beg; e < end; e++) {
        int s = csrc[e];
        float a = cattr[e];
        size_t r = (size_t)s * FF;
        a00 += a * in0[r + lane];  a01 += a * in0[r + 32 + lane];
        a10 += a * in1[r + lane];  a11 += a * in1[r + 32 + lane];
        a20 += a * in2[r + lane];  a21 += a * in2[r + 32 + lane];
    }
    size_t w = (size_t)warp * FF;
    o0[w + lane] = a00;  o0[w + 32 + lane] = a01;
    o1[w + lane] = a10;  o1[w + 32 + lane] = a11;
    o2[w + lane] = a20;  o2[w + 32 + lane] = a21;
}

// ---------------- GEMM (fp32, 64x64 tile, BK=16, 4x4/thread) ----------------
__global__ void gemm_kernel(const float* __restrict__ A, const float* __restrict__ B,
                            const float* __restrict__ bias, float* __restrict__ C,
                            int M, int Nc, int K) {
    __shared__ float As[16][68];
    __shared__ float Bs[16][68];
    int tid = threadIdx.x;
    int tx = tid & 15, ty = tid >> 4;
    int nb = Nc >> 6;
    int bn = (blockIdx.x % nb) * 64;
    int bm = (blockIdx.x / nb) * 64;
    float acc[4][4] = {};
    for (int k0 = 0; k0 < K; k0 += 16) {
        {
            int m = tid >> 2;
            int kk = (tid & 3) * 4;
            float4 v = *(const float4*)(A + (size_t)(bm + m) * K + k0 + kk);
            As[kk + 0][m] = v.x; As[kk + 1][m] = v.y; As[kk + 2][m] = v.z; As[kk + 3][m] = v.w;
        }
        {
            int kk = tid >> 4;
            int n = (tid & 15) * 4;
            *(float4*)&Bs[kk][n] = *(const float4*)(B + (size_t)(k0 + kk) * Nc + bn + n);
        }
        __syncthreads();
#pragma unroll
        for (int kk = 0; kk < 16; kk++) {
            float4 a = *(float4*)&As[kk][ty * 4];
            float4 b = *(float4*)&Bs[kk][tx * 4];
            acc[0][0] += a.x * b.x; acc[0][1] += a.x * b.y; acc[0][2] += a.x * b.z; acc[0][3] += a.x * b.w;
            acc[1][0] += a.y * b.x; acc[1][1] += a.y * b.y; acc[1][2] += a.y * b.z; acc[1][3] += a.y * b.w;
            acc[2][0] += a.z * b.x; acc[2][1] += a.z * b.y; acc[2][2] += a.z * b.z; acc[2][3] += a.z * b.w;
            acc[3][0] += a.w * b.x; acc[3][1] += a.w * b.y; acc[3][2] += a.w * b.z; acc[3][3] += a.w * b.w;
        }
        __syncthreads();
    }
#pragma unroll
    for (int i = 0; i < 4; i++) {
#pragma unroll
        for (int j = 0; j < 4; j++) {
            float v = acc[i][j];
            if (bias) v += bias[bn + tx * 4 + j];
            C[(size_t)(bm + ty * 4 + i) * Nc + bn + tx * 4 + j] = v;
        }
    }
}

// ---------------- GAT pieces ----------------
// a_s[n,h] = <h[n,h,:], asrc[h,:]>, a_d likewise. warp per (n,h).
__global__ void asad_kernel(const float* __restrict__ h, const float* __restrict__ asrc,
                            const float* __restrict__ adst, float* __restrict__ a_s,
                            float* __restrict__ a_d) {
    int warp = (blockIdx.x * blockDim.x + threadIdx.x) >> 5;
    int lane = threadIdx.x & 31;
    if (warp >= NN * HH) return;
    int n = warp >> 2, hh = warp & 3;
    float2 hv = *(const float2*)(h + (size_t)n * HF + hh * FF + lane * 2);
    float2 ws = *(const float2*)(asrc + hh * FF + lane * 2);
    float2 wd = *(const float2*)(adst + hh * FF + lane * 2);
    float ss = hv.x * ws.x + hv.y * ws.y;
    float dd = hv.x * wd.x + hv.y * wd.y;
    for (int o = 16; o; o >>= 1) {
        ss += __shfl_down_sync(0xffffffffu, ss, o);
        dd += __shfl_down_sync(0xffffffffu, dd, o);
    }
    if (lane == 0) { a_s[warp] = ss; a_d[warp] = dd; }
}

// full GAT attention aggregation per node (warp per node): max, exp, denom,
// weighted sum of h[src], /denom + bias + elu — all in registers. Self-loop included.
__global__ void gat_agg_kernel(const int* __restrict__ rowptr, const int* __restrict__ csrc,
                               const float* __restrict__ a_s, const float* __restrict__ a_d,
                               const float* __restrict__ h, const float* __restrict__ gb,
                               float* __restrict__ outx) {
    int warp = (blockIdx.x * blockDim.x + threadIdx.x) >> 5;
    int lane = threadIdx.x & 31;
    if (warp >= NN) return;
    int d = warp;
    int beg = rowptr[d], end = rowptr[d + 1];
    float4 ad4 = *(const float4*)(a_d + (size_t)d * 4);
    float4 sf4 = *(const float4*)(a_s + (size_t)d * 4);
    float sl0 = lrelu(sf4.x + ad4.x);
    float sl1 = lrelu(sf4.y + ad4.y);
    float sl2 = lrelu(sf4.z + ad4.z);
    float sl3 = lrelu(sf4.w + ad4.w);
    float m0 = sl0, m1 = sl1, m2 = sl2, m3 = sl3;
    // pass 1: segment max (lanes parallel over edges)
    for (int e = beg + lane; e < end; e += 32) {
        int s = csrc[e];
        float4 s4 = *(const float4*)(a_s + (size_t)s * 4);
        m0 = fmaxf(m0, lrelu(s4.x + ad4.x));
        m1 = fmaxf(m1, lrelu(s4.y + ad4.y));
        m2 = fmaxf(m2, lrelu(s4.z + ad4.z));
        m3 = fmaxf(m3, lrelu(s4.w + ad4.w));
    }
    for (int o = 16; o; o >>= 1) {
        m0 = fmaxf(m0, __shfl_xor_sync(0xffffffffu, m0, o));
        m1 = fmaxf(m1, __shfl_xor_sync(0xffffffffu, m1, o));
        m2 = fmaxf(m2, __shfl_xor_sync(0xffffffffu, m2, o));
        m3 = fmaxf(m3, __shfl_xor_sync(0xffffffffu, m3, o));
    }
    // pass 2: self-loop contribution
    float acc[8];
    float den0, den1, den2, den3;
    {
        float e0 = expf(sl0 - m0), e1 = expf(sl1 - m1);
        float e2 = expf(sl2 - m2), e3 = expf(sl3 - m3);
        den0 = e0; den1 = e1; den2 = e2; den3 = e3;
        const float* hp = h + (size_t)d * HF;
        acc[0] = e0 * hp[lane];        acc[1] = e0 * hp[32 + lane];
        acc[2] = e1 * hp[64 + lane];   acc[3] = e1 * hp[96 + lane];
        acc[4] = e2 * hp[128 + lane];  acc[5] = e2 * hp[160 + lane];
        acc[6] = e3 * hp[192 + lane];  acc[7] = e3 * hp[224 + lane];
    }
    // edges: exps computed lane-parallel per 32-chunk, broadcast via shfl
    for (int c0 = beg; c0 < end; c0 += 32) {
        int e = c0 + lane;
        int sl = 0;
        float x0 = 0.f, x1 = 0.f, x2 = 0.f, x3 = 0.f;
        if (e < end) {
            sl = csrc[e];
            float4 s4 = *(const float4*)(a_s + (size_t)sl * 4);
            x0 = expf(lrelu(s4.x + ad4.x) - m0);
            x1 = expf(lrelu(s4.y + ad4.y) - m1);
            x2 = expf(lrelu(s4.z + ad4.z) - m2);
            x3 = expf(lrelu(s4.w + ad4.w) - m3);
        }
        int cnt = min(32, end - c0);
        for (int i = 0; i < cnt; i++) {
            int s   = __shfl_sync(0xffffffffu, sl, i);
            float e0 = __shfl_sync(0xffffffffu, x0, i);
            float e1 = __shfl_sync(0xffffffffu, x1, i);
            float e2 = __shfl_sync(0xffffffffu, x2, i);
            float e3 = __shfl_sync(0xffffffffu, x3, i);
            den0 += e0; den1 += e1; den2 += e2; den3 += e3;
            const float* hp = h + (size_t)s * HF;
            acc[0] += e0 * hp[lane];        acc[1] += e0 * hp[32 + lane];
            acc[2] += e1 * hp[64 + lane];   acc[3] += e1 * hp[96 + lane];
            acc[4] += e2 * hp[128 + lane];  acc[5] += e2 * hp[160 + lane];
            acc[6] += e3 * hp[192 + lane];  acc[7] += e3 * hp[224 + lane];
        }
    }
    float den[4] = {den0, den1, den2, den3};
    float* op = outx + (size_t)d * HF;
#pragma unroll
    for (int j = 0; j < 8; j++) {
        int c = j * 32 + lane;
        op[c] = elu(acc[j] / den[j >> 1] + gb[c]);
    }
}

// ---------------- BatchNorm (2-stage, coalesced) ----------------
// stage 1: 256 blocks x 256 threads; block b covers rows [b*128,(b+1)*128)
__global__ void bnstat1_kernel(const float* __restrict__ z, double* __restrict__ part) {
    int b = blockIdx.x;
    int t = threadIdx.x;
    int c = t & 63;
    int rg = t >> 6;            // 4 row groups of 32 rows
    int r0 = b * 128 + rg * 32;
    double s = 0.0, q = 0.0;
    for (int i = 0; i < 32; i++) {
        float v = z[(size_t)(r0 + i) * FF + c];
        s += v; q += (double)v * v;
    }
    __shared__ double shs[256], shq[256];
    shs[t] = s; shq[t] = q;
    __syncthreads();
    if (rg == 0) {
        s = shs[c] + shs[64 + c] + shs[128 + c] + shs[192 + c];
        q = shq[c] + shq[64 + c] + shq[128 + c] + shq[192 + c];
        part[(size_t)b * FF * 2 + c * 2 + 0] = s;
        part[(size_t)b * FF * 2 + c * 2 + 1] = q;
    }
}
// stage 2: 1 block x 256 threads
__global__ void bnstat2_kernel(const double* __restrict__ part,
                               float* __restrict__ mu_out, float* __restrict__ rstd_out) {
    int t = threadIdx.x;
    int c = t & 63;
    int cg = t >> 6;            // 4 chunks of 64 partial blocks
    double s = 0.0, q = 0.0;
    for (int i = cg * 64; i < (cg + 1) * 64; i++) {
        s += part[(size_t)i * FF * 2 + c * 2 + 0];
        q += part[(size_t)i * FF * 2 + c * 2 + 1];
    }
    __shared__ double shs[256], shq[256];
    shs[t] = s; shq[t] = q;
    __syncthreads();
    if (cg == 0) {
        s = shs[c] + shs[64 + c] + shs[128 + c] + shs[192 + c];
        q = shq[c] + shq[64 + c] + shq[128 + c] + shq[192 + c];
        double mu = s / NN;
        double var = q / NN - mu * mu;
        mu_out[c] = (float)mu;
        rstd_out[c] = rsqrtf((float)var + BNEPS);
    }
}

__global__ void bnapply_kernel(const float* __restrict__ z, const float* __restrict__ g,
                               const float* __restrict__ beta, float* __restrict__ acc,
                               const float* __restrict__ mu, const float* __restrict__ rstd) {
    int idx = blockIdx.x * blockDim.x + threadIdx.x;
    if (idx >= NN * FF) return;
    int f = idx & 63;
    acc[idx] += (z[idx] - mu[f]) * rstd[f] * g[f] + beta[f];
}

// ---------------- pooling + FC head ----------------
__global__ void pool_kernel(const float* __restrict__ acc, const int* __restrict__ batch,
                            float* __restrict__ pooled) {
    int idx = blockIdx.x * blockDim.x + threadIdx.x;
    if (idx >= NN * FF) return;
    int n = idx >> 6, f = idx & 63;
    atomicAdd(&pooled[batch[n] * FF + f], acc[idx]);
}

__global__ void fcbn_kernel(const float* __restrict__ A, const float* __restrict__ W,
                            const float* __restrict__ b, const float* __restrict__ g,
                            const float* __restrict__ beta, float* __restrict__ out,
                            int K, int Nc, int do_relu) {
    int j = blockIdx.x;
    int r = threadIdx.x;
    float y = b[j];
    for (int k = 0; k < K; k++) y += A[r * K + k] * W[k * Nc + j];
    __shared__ float sh[GG];
    __shared__ float s_mu, s_var;
    sh[r] = y;
    __syncthreads();
    if (r == 0) {
        float s = 0.f;
        for (int i = 0; i < GG; i++) s += sh[i];
        float mu = s / GG;
        float q = 0.f;
        for (int i = 0; i < GG; i++) { float dd = sh[i] - mu; q += dd * dd; }
        s_mu = mu; s_var = q / GG;
    }
    __syncthreads();
    float o = (y - s_mu) * rsqrtf(s_var + BNEPS) * g[j] + beta[j];
    if (do_relu) o = fmaxf(o, 0.f);
    out[r * Nc + j] = o;
}

// ---------------- launch ----------------
static inline void* sym(const void* s) {
    void* p = nullptr;
    cudaGetSymbolAddress(&p, s);
    return p;
}

extern "C" void kernel_launch(void* const* d_in, const int* in_sizes, int n_in,
                              void* d_out, int out_size) {
    const float* x       = (const float*)d_in[0];
    const int*  eidx     = (const int*)d_in[1];
    const int*  batch    = (const int*)d_in[2];
    const int*  sidx     = (const int*)d_in[3];
    const float* sattr   = (const float*)d_in[4];
    const float* gat_W   = (const float*)d_in[5];
    const float* gat_as  = (const float*)d_in[6];
    const float* gat_ad  = (const float*)d_in[7];
    const float* gat_b   = (const float*)d_in[8];
    const float* mlp_W   = (const float*)d_in[9];
    const float* mlp_b   = (const float*)d_in[10];
    const float* mlp_g   = (const float*)d_in[11];
    const float* mlp_be  = (const float*)d_in[12];
    const float* fc1_W   = (const float*)d_in[13];
    const float* fc1_b   = (const float*)d_in[14];
    const float* fc1_g   = (const float*)d_in[15];
    const float* fc1_be  = (const float*)d_in[16];
    const float* fc2_W   = (const float*)d_in[17];
    const float* fc2_b   = (const float*)d_in[18];
    const float* fc2_g   = (const float*)d_in[19];
    const float* fc2_be  = (const float*)d_in[20];
    const float* fc3_W   = (const float*)d_in[21];
    const float* fc3_b   = (const float*)d_in[22];
    const float* fc3_g   = (const float*)d_in[23];
    const float* fc3_be  = (const float*)d_in[24];
    float* out = (float*)d_out;

    float* p_xs     = (float*)sym(d_xs);
    float* p_xh     = (float*)sym(d_xh);
    float* p_h      = (float*)sym(d_h);
    float* p_as     = (float*)sym(d_as);
    float* p_ad     = (float*)sym(d_ad);
    float* p_gacc   = (float*)sym(d_gacc);
    float* p_z      = (float*)sym(d_z);
    float* p_acc    = (float*)sym(d_acc);
    double* p_bnpart = (double*)sym(d_bnpart);
    float* p_bnmu   = (float*)sym(d_bnmu);
    float* p_bnrstd = (float*)sym(d_bnrstd);
    float* p_pooled = (float*)sym(d_pooled);
    float* p_h1     = (float*)sym(d_h1);
    float* p_h2     = (float*)sym(d_h2);
    int*   p_cnt    = (int*)sym(d_cnt);
    int*   p_rowptr = (int*)sym(d_rowptr);
    int*   p_csrc   = (int*)sym(d_csrc);
    float* p_cattr  = (float*)sym(d_cattr);

    const int TB = 256;
    const int EB = (ESZ + TB - 1) / TB;
    const int NW = (NN * 32 + TB - 1) / TB;   // warp-per-node grids

    // ---- build 5 CSRs: scatter graphs 0..3, gat edges (id 4) ----
    for (int g = 0; g < 5; g++) {
        const int* gsrc; const int* gdst; const float* gattr; float* gcattr;
        if (g < 4) {
            gsrc = sidx + g * 2 * ESZ;
            gdst = gsrc + ESZ;
            gattr = sattr + g * ESZ;
            gcattr = p_cattr + (size_t)g * ESZ;
        } else {
            gsrc = eidx;
            gdst = eidx + EGZ;
            gattr = nullptr;
            gcattr = nullptr;
        }
        int* rp = p_rowptr + (size_t)g * (NN + 1);
        int* cs = p_csrc + (size_t)g * ESZ;
        zero_i_kernel<<<(2 * NN + TB - 1) / TB, TB>>>(p_cnt, 2 * NN);
        hist_kernel<<<EB, TB>>>(gdst, p_cnt, ESZ);
        scan_kernel<<<1, 1024>>>(p_cnt, rp);
        fill_kernel<<<EB, TB>>>(gsrc, gdst, gattr, rp, p_cnt + NN, cs, gcattr, ESZ);
    }

    // ---- solo passes (gather form) ----
    gather1_kernel<<<NW, TB>>>(p_rowptr, p_csrc, p_cattr, x, p_xs, 0);
    for (int k = 1; k < 4; k++) {
        gather1_kernel<<<NW, TB>>>(p_rowptr + (size_t)k * (NN + 1), p_csrc + (size_t)k * ESZ,
                                   p_cattr + (size_t)k * ESZ, x,
                                   p_xh + (size_t)(k - 1) * NN * FF, 1);
    }
    gather3_kernel<<<NW, TB>>>(p_rowptr, p_csrc, p_cattr,
                               p_xh, p_xh + (size_t)NN * FF, p_xh + (size_t)2 * NN * FF,
                               p_xs + (size_t)NN * FF, p_xs + (size_t)2 * NN * FF,
                               p_xs + (size_t)3 * NN * FF);

    // ---- residual accumulator = x ----
    copy_kernel<<<(NN * FF / 4 + TB - 1) / TB, TB>>>((const float4*)x, (float4*)p_acc, NN * FF / 4);

    // ---- 4 GAT + MLP + BN layers ----
    const int* gat_rp = p_rowptr + (size_t)4 * (NN + 1);
    const int* gat_cs = p_csrc + (size_t)4 * ESZ;
    for (int i = 0; i < 4; i++) {
        gemm_kernel<<<(NN / 64) * (HF / 64), TB>>>(p_xs + (size_t)i * NN * FF,
                                                   gat_W + (size_t)i * FF * HF,
                                                   nullptr, p_h, NN, HF, FF);
        asad_kernel<<<(NN * HH * 32 + TB - 1) / TB, TB>>>(p_h, gat_as + (size_t)i * HH * FF,
                                                          gat_ad + (size_t)i * HH * FF, p_as, p_ad);
        gat_agg_kernel<<<NW, TB>>>(gat_rp, gat_cs, p_as, p_ad, p_h,
                                   gat_b + (size_t)i * HF, p_gacc);
        gemm_kernel<<<(NN / 64) * (FF / 64), TB>>>(p_gacc, mlp_W + (size_t)i * HF * FF,
                                                   mlp_b + (size_t)i * FF, p_z, NN, FF, HF);
        bnstat1_kernel<<<256, 256>>>(p_z, p_bnpart);
        bnstat2_kernel<<<1, 256>>>(p_bnpart, p_bnmu, p_bnrstd);
        bnapply_kernel<<<(NN * FF + TB - 1) / TB, TB>>>(p_z, mlp_g + (size_t)i * FF,
                                                        mlp_be + (size_t)i * FF,
                                                        p_acc, p_bnmu, p_bnrstd);
    }

    // ---- pooling + FC head ----
    zero_f_kernel<<<(GG * FF / 4 + TB - 1) / TB, TB>>>((float4*)p_pooled, GG * FF / 4);
    pool_kernel<<<(NN * FF + TB - 1) / TB, TB>>>(p_acc, batch, p_pooled);
    fcbn_kernel<<<256, GG>>>(p_pooled, fc1_W, fc1_b, fc1_g, fc1_be, p_h1, 64, 256, 1);
    fcbn_kernel<<<128, GG>>>(p_h1, fc2_W, fc2_b, fc2_g, fc2_be, p_h2, 256, 128, 1);
    fcbn_kernel<<<NCLS, GG>>>(p_h2, fc3_W, fc3_b, fc3_g, fc3_be, out, 128, NCLS, 0);
}

// round 6
// speedup vs baseline: 1.5492x; 1.1796x over previous
#include <cuda_runtime.h>
#include <math.h>

#define NN   32768
#define FF   64
#define HH   4
#define HF   256
#define ESZ  524288
#define EGZ  524288
#define GG   64
#define NCLS 10
#define BNEPS 1e-5f

// ---------------- device scratch (static allocation only) ----------------
__device__ float  d_xs[4][NN*FF];     // x0..x3 (GAT inputs)
__device__ float  d_xh[3][NN*FF];     // xh1..xh3 intermediates
__device__ float  d_h[NN*HF];         // h = x @ W   [N,256]
__device__ float  d_as[NN*HH];
__device__ float  d_ad[NN*HH];
__device__ float  d_gacc[NN*HF];      // elu(gat output)
__device__ float  d_z[NN*FF];         // mlp output
__device__ float  d_acc[NN*FF];       // running residual x + sum(bn_out)
__device__ float  d_bnpart[512*FF*2]; // per-block (sum,sumsq) partials from gemm_bn
__device__ float  d_bnmu[FF];
__device__ float  d_bnrstd[FF];
__device__ float  d_pooled[GG*FF];
__device__ float  d_h1[GG*256];
__device__ float  d_h2[GG*128];
// CSR scratch: ids 0..3 = scatter graphs, 4 = gat edge graph
__device__ int    d_cnt[5][2*NN];     // per graph: [0,NN)=hist, [NN,2NN)=cursor
__device__ int    d_rowptr[5][NN+1];
__device__ int    d_csrc[5][ESZ];
__device__ float  d_cattr[4][ESZ];

// ---------------- helpers ----------------
__device__ __forceinline__ float lrelu(float x) { return x >= 0.f ? x : 0.2f * x; }
__device__ __forceinline__ float elu(float x)   { return x > 0.f ? x : expm1f(x); }

__global__ void zero_i_kernel(int* p, int n) {
    int i = blockIdx.x * blockDim.x + threadIdx.x;
    if (i < n) p[i] = 0;
}
__global__ void zero_f_kernel(float4* p, int n4) {
    int i = blockIdx.x * blockDim.x + threadIdx.x;
    if (i < n4) p[i] = make_float4(0.f, 0.f, 0.f, 0.f);
}
__global__ void copy_kernel(const float4* __restrict__ in, float4* __restrict__ out, int n4) {
    int i = blockIdx.x * blockDim.x + threadIdx.x;
    if (i < n4) out[i] = in[i];
}

// ---------------- batched CSR build (5 graphs at once) ----------------
__global__ void hist5_kernel(const int* __restrict__ sidx, const int* __restrict__ eidx,
                             int* __restrict__ cnt) {
    int g = blockIdx.y;
    const int* dst = (g < 4) ? (sidx + (size_t)g * 2 * ESZ + ESZ) : (eidx + EGZ);
    int e = blockIdx.x * blockDim.x + threadIdx.x;
    if (e < ESZ) atomicAdd(&cnt[(size_t)g * 2 * NN + dst[e]], 1);
}

// exclusive scan over NN counts; block per graph, 1024 threads, 32/thread
__global__ void scan5_kernel(const int* __restrict__ cnt_all, int* __restrict__ rowptr_all) {
    int g = blockIdx.x;
    const int* cnt = cnt_all + (size_t)g * 2 * NN;
    int* rowptr = rowptr_all + (size_t)g * (NN + 1);
    __shared__ int sh[1024];
    int t = threadIdx.x;
    int base = t * 32;
    int local[32];
    int s = 0;
#pragma unroll
    for (int i = 0; i < 32; i++) { local[i] = s; s += cnt[base + i]; }
    sh[t] = s;
    __syncthreads();
    for (int o = 1; o < 1024; o <<= 1) {
        int v = (t >= o) ? sh[t - o] : 0;
        __syncthreads();
        sh[t] += v;
        __syncthreads();
    }
    int off = (t == 0) ? 0 : sh[t - 1];
#pragma unroll
    for (int i = 0; i < 32; i++) rowptr[base + i] = off + local[i];
    if (t == 1023) rowptr[NN] = sh[1023];
}

__global__ void fill5_kernel(const int* __restrict__ sidx, const int* __restrict__ eidx,
                             const float* __restrict__ sattr,
                             const int* __restrict__ rowptr_all, int* __restrict__ cnt_all,
                             int* __restrict__ csrc_all, float* __restrict__ cattr_all) {
    int g = blockIdx.y;
    const int* src; const int* dst; const float* attr;
    if (g < 4) {
        src = sidx + (size_t)g * 2 * ESZ;
        dst = src + ESZ;
        attr = sattr + (size_t)g * ESZ;
    } else {
        src = eidx; dst = eidx + EGZ; attr = nullptr;
    }
    int e = blockIdx.x * blockDim.x + threadIdx.x;
    if (e >= ESZ) return;
    int d = dst[e];
    const int* rowptr = rowptr_all + (size_t)g * (NN + 1);
    int* cursor = cnt_all + (size_t)g * 2 * NN + NN;
    int pos = rowptr[d] + atomicAdd(&cursor[d], 1);
    csrc_all[(size_t)g * ESZ + pos] = src[e];
    if (attr) cattr_all[(size_t)g * ESZ + pos] = attr[e];
}

// ---------------- CSR gathers (warp per node) ----------------
// grid.y = 4: g=0 -> xs0 (no abs), g=1..3 -> xh[g-1] (abs)
__global__ void gatherA_kernel(const int* __restrict__ rowptr_all, const int* __restrict__ csrc_all,
                               const float* __restrict__ cattr_all, const float* __restrict__ in,
                               float* __restrict__ xs0, float* __restrict__ xh_base) {
    int g = blockIdx.y;
    const int* rowptr = rowptr_all + (size_t)g * (NN + 1);
    const int* csrc = csrc_all + (size_t)g * ESZ;
    const float* cattr = cattr_all + (size_t)g * ESZ;
    int warp = (blockIdx.x * blockDim.x + threadIdx.x) >> 5;
    int lane = threadIdx.x & 31;
    if (warp >= NN) return;
    int beg = rowptr[warp], end = rowptr[warp + 1];
    float a0 = 0.f, a1 = 0.f;
    for (int e = beg; e < end; e++) {
        int s = csrc[e];
        float a = cattr[e];
        const float* ip = in + (size_t)s * FF;
        a0 += a * ip[lane];
        a1 += a * ip[32 + lane];
    }
    float* out = (g == 0) ? xs0 : (xh_base + (size_t)(g - 1) * NN * FF);
    if (g > 0) { a0 = fabsf(a0); a1 = fabsf(a1); }
    float* op = out + (size_t)warp * FF;
    op[lane] = a0;
    op[32 + lane] = a1;
}

// three inputs through graph-0 CSR
__global__ void gather3_kernel(const int* __restrict__ rowptr, const int* __restrict__ csrc,
                               const float* __restrict__ cattr,
                               const float* __restrict__ in0, const float* __restrict__ in1,
                               const float* __restrict__ in2,
                               float* __restrict__ o0, float* __restrict__ o1,
                               float* __restrict__ o2) {
    int warp = (blockIdx.x * blockDim.x + threadIdx.x) >> 5;
    int lane = threadIdx.x & 31;
    if (warp >= NN) return;
    int beg = rowptr[warp], end = rowptr[warp + 1];
    float a00 = 0.f, a01 = 0.f, a10 = 0.f, a11 = 0.f, a20 = 0.f, a21 = 0.f;
    for (int e = beg; e < end; e++) {
        int s = csrc[e];
        float a = cattr[e];
        size_t r = (size_t)s * FF;
        a00 += a * in0[r + lane];  a01 += a * in0[r + 32 + lane];
        a10 += a * in1[r + lane];  a11 += a * in1[r + 32 + lane];
        a20 += a * in2[r + lane];  a21 += a * in2[r + 32 + lane];
    }
    size_t w = (size_t)warp * FF;
    o0[w + lane] = a00;  o0[w + 32 + lane] = a01;
    o1[w + lane] = a10;  o1[w + 32 + lane] = a11;
    o2[w + lane] = a20;  o2[w + 32 + lane] = a21;
}

// ---------------- GEMM 1: h = A@W, fused a_s/a_d epilogue ----------------
// M=NN, Nc=256 (nb=4, each 64-col tile == one attention head), K=64.
__global__ void gemm_asad_kernel(const float* __restrict__ A, const float* __restrict__ B,
                                 float* __restrict__ C,
                                 const float* __restrict__ asrc, const float* __restrict__ adst,
                                 float* __restrict__ a_s, float* __restrict__ a_d) {
    const int K = FF, Nc = HF;
    __shared__ float As[16][68];
    __shared__ float Bs[16][68];
    __shared__ float shs[64][17];
    __shared__ float shd[64][17];
    int tid = threadIdx.x;
    int tx = tid & 15, ty = tid >> 4;
    int bn = (blockIdx.x & 3) * 64;
    int bm = (blockIdx.x >> 2) * 64;
    float acc[4][4] = {};
    for (int k0 = 0; k0 < K; k0 += 16) {
        {
            int m = tid >> 2;
            int kk = (tid & 3) * 4;
            float4 v = *(const float4*)(A + (size_t)(bm + m) * K + k0 + kk);
            As[kk + 0][m] = v.x; As[kk + 1][m] = v.y; As[kk + 2][m] = v.z; As[kk + 3][m] = v.w;
        }
        {
            int kk = tid >> 4;
            int n = (tid & 15) * 4;
            *(float4*)&Bs[kk][n] = *(const float4*)(B + (size_t)(k0 + kk) * Nc + bn + n);
        }
        __syncthreads();
#pragma unroll
        for (int kk = 0; kk < 16; kk++) {
            float4 a = *(float4*)&As[kk][ty * 4];
            float4 b = *(float4*)&Bs[kk][tx * 4];
            acc[0][0] += a.x * b.x; acc[0][1] += a.x * b.y; acc[0][2] += a.x * b.z; acc[0][3] += a.x * b.w;
            acc[1][0] += a.y * b.x; acc[1][1] += a.y * b.y; acc[1][2] += a.y * b.z; acc[1][3] += a.y * b.w;
            acc[2][0] += a.z * b.x; acc[2][1] += a.z * b.y; acc[2][2] += a.z * b.z; acc[2][3] += a.z * b.w;
            acc[3][0] += a.w * b.x; acc[3][1] += a.w * b.y; acc[3][2] += a.w * b.z; acc[3][3] += a.w * b.w;
        }
        __syncthreads();
    }
    // store C
#pragma unroll
    for (int i = 0; i < 4; i++) {
#pragma unroll
        for (int j = 0; j < 4; j++) {
            C[(size_t)(bm + ty * 4 + i) * Nc + bn + tx * 4 + j] = acc[i][j];
        }
    }
    // fused head-dot: this block's 64 cols = head hh
    int hh = bn >> 6;
    float ws[4], wd[4];
#pragma unroll
    for (int j = 0; j < 4; j++) {
        ws[j] = asrc[hh * 64 + tx * 4 + j];
        wd[j] = adst[hh * 64 + tx * 4 + j];
    }
#pragma unroll
    for (int i = 0; i < 4; i++) {
        float ps = acc[i][0] * ws[0] + acc[i][1] * ws[1] + acc[i][2] * ws[2] + acc[i][3] * ws[3];
        float pd = acc[i][0] * wd[0] + acc[i][1] * wd[1] + acc[i][2] * wd[2] + acc[i][3] * wd[3];
        shs[ty * 4 + i][tx] = ps;
        shd[ty * 4 + i][tx] = pd;
    }
    __syncthreads();
    if (tid < 64) {
        float s = 0.f, dd = 0.f;
#pragma unroll
        for (int t = 0; t < 16; t++) { s += shs[tid][t]; dd += shd[tid][t]; }
        a_s[(size_t)(bm + tid) * 4 + hh] = s;
        a_d[(size_t)(bm + tid) * 4 + hh] = dd;
    }
}

// ---------------- GEMM 2: z = A@W + b, fused BN partial stats ----------------
// M=NN, Nc=64 (nb=1), K=256. part[blk][col][2] = (sum, sumsq) over the 64-row tile.
__global__ void gemm_bn_kernel(const float* __restrict__ A, const float* __restrict__ B,
                               const float* __restrict__ bias, float* __restrict__ C,
                               float* __restrict__ part) {
    const int K = HF, Nc = FF;
    __shared__ float As[16][68];
    __shared__ float Bs[16][68];
    __shared__ float shs[64][17];
    __shared__ float shq[64][17];
    int tid = threadIdx.x;
    int tx = tid & 15, ty = tid >> 4;
    int bm = blockIdx.x * 64;
    float acc[4][4] = {};
    for (int k0 = 0; k0 < K; k0 += 16) {
        {
            int m = tid >> 2;
            int kk = (tid & 3) * 4;
            float4 v = *(const float4*)(A + (size_t)(bm + m) * K + k0 + kk);
            As[kk + 0][m] = v.x; As[kk + 1][m] = v.y; As[kk + 2][m] = v.z; As[kk + 3][m] = v.w;
        }
        {
            int kk = tid >> 4;
            int n = (tid & 15) * 4;
            *(float4*)&Bs[kk][n] = *(const float4*)(B + (size_t)(k0 + kk) * Nc + n);
        }
        __syncthreads();
#pragma unroll
        for (int kk = 0; kk < 16; kk++) {
            float4 a = *(float4*)&As[kk][ty * 4];
            float4 b = *(float4*)&Bs[kk][tx * 4];
            acc[0][0] += a.x * b.x; acc[0][1] += a.x * b.y; acc[0][2] += a.x * b.z; acc[0][3] += a.x * b.w;
            acc[1][0] += a.y * b.x; acc[1][1] += a.y * b.y; acc[1][2] += a.y * b.z; acc[1][3] += a.y * b.w;
            acc[2][0] += a.z * b.x; acc[2][1] += a.z * b.y; acc[2][2] += a.z * b.z; acc[2][3] += a.z * b.w;
            acc[3][0] += a.w * b.x; acc[3][1] += a.w * b.y; acc[3][2] += a.w * b.z; acc[3][3] += a.w * b.w;
        }
        __syncthreads();
    }
    float bs[4];
#pragma unroll
    for (int j = 0; j < 4; j++) bs[j] = bias[tx * 4 + j];
    float colsum[4] = {}, colsq[4] = {};
#pragma unroll
    for (int i = 0; i < 4; i++) {
#pragma unroll
        for (int j = 0; j < 4; j++) {
            float v = acc[i][j] + bs[j];
            C[(size_t)(bm + ty * 4 + i) * Nc + tx * 4 + j] = v;
            colsum[j] += v;
            colsq[j]  += v * v;
        }
    }
#pragma unroll
    for (int j = 0; j < 4; j++) {
        shs[tx * 4 + j][ty] = colsum[j];
        shq[tx * 4 + j][ty] = colsq[j];
    }
    __syncthreads();
    if (tid < 64) {
        float s = 0.f, q = 0.f;
#pragma unroll
        for (int t = 0; t < 16; t++) { s += shs[tid][t]; q += shq[tid][t]; }
        part[((size_t)blockIdx.x * 64 + tid) * 2 + 0] = s;
        part[((size_t)blockIdx.x * 64 + tid) * 2 + 1] = q;
    }
}

// reduce 512 block partials -> mu, rstd
__global__ void bnstat2_kernel(const float* __restrict__ part,
                               float* __restrict__ mu_out, float* __restrict__ rstd_out) {
    int t = threadIdx.x;
    int c = t & 63;
    int cg = t >> 6;            // 4 chunks of 128 blocks
    double s = 0.0, q = 0.0;
    for (int b = cg * 128; b < (cg + 1) * 128; b++) {
        s += part[((size_t)b * 64 + c) * 2 + 0];
        q += part[((size_t)b * 64 + c) * 2 + 1];
    }
    __shared__ double shs[256], shq[256];
    shs[t] = s; shq[t] = q;
    __syncthreads();
    if (cg == 0) {
        s = shs[c] + shs[64 + c] + shs[128 + c] + shs[192 + c];
        q = shq[c] + shq[64 + c] + shq[128 + c] + shq[192 + c];
        double mu = s / NN;
        double var = q / NN - mu * mu;
        mu_out[c] = (float)mu;
        rstd_out[c] = rsqrtf((float)var + BNEPS);
    }
}

// ---------------- GAT aggregation (warp per node) ----------------
__global__ void gat_agg_kernel(const int* __restrict__ rowptr, const int* __restrict__ csrc,
                               const float* __restrict__ a_s, const float* __restrict__ a_d,
                               const float* __restrict__ h, const float* __restrict__ gb,
                               float* __restrict__ outx) {
    int warp = (blockIdx.x * blockDim.x + threadIdx.x) >> 5;
    int lane = threadIdx.x & 31;
    if (warp >= NN) return;
    int d = warp;
    int beg = rowptr[d], end = rowptr[d + 1];
    float4 ad4 = *(const float4*)(a_d + (size_t)d * 4);
    float4 sf4 = *(const float4*)(a_s + (size_t)d * 4);
    float sl0 = lrelu(sf4.x + ad4.x);
    float sl1 = lrelu(sf4.y + ad4.y);
    float sl2 = lrelu(sf4.z + ad4.z);
    float sl3 = lrelu(sf4.w + ad4.w);
    float m0 = sl0, m1 = sl1, m2 = sl2, m3 = sl3;
    for (int e = beg + lane; e < end; e += 32) {
        int s = csrc[e];
        float4 s4 = *(const float4*)(a_s + (size_t)s * 4);
        m0 = fmaxf(m0, lrelu(s4.x + ad4.x));
        m1 = fmaxf(m1, lrelu(s4.y + ad4.y));
        m2 = fmaxf(m2, lrelu(s4.z + ad4.z));
        m3 = fmaxf(m3, lrelu(s4.w + ad4.w));
    }
    for (int o = 16; o; o >>= 1) {
        m0 = fmaxf(m0, __shfl_xor_sync(0xffffffffu, m0, o));
        m1 = fmaxf(m1, __shfl_xor_sync(0xffffffffu, m1, o));
        m2 = fmaxf(m2, __shfl_xor_sync(0xffffffffu, m2, o));
        m3 = fmaxf(m3, __shfl_xor_sync(0xffffffffu, m3, o));
    }
    float acc[8];
    float den0, den1, den2, den3;
    {
        float e0 = expf(sl0 - m0), e1 = expf(sl1 - m1);
        float e2 = expf(sl2 - m2), e3 = expf(sl3 - m3);
        den0 = e0; den1 = e1; den2 = e2; den3 = e3;
        const float* hp = h + (size_t)d * HF;
        acc[0] = e0 * hp[lane];        acc[1] = e0 * hp[32 + lane];
        acc[2] = e1 * hp[64 + lane];   acc[3] = e1 * hp[96 + lane];
        acc[4] = e2 * hp[128 + lane];  acc[5] = e2 * hp[160 + lane];
        acc[6] = e3 * hp[192 + lane];  acc[7] = e3 * hp[224 + lane];
    }
    for (int c0 = beg; c0 < end; c0 += 32) {
        int e = c0 + lane;
        int sl = 0;
        float x0 = 0.f, x1 = 0.f, x2 = 0.f, x3 = 0.f;
        if (e < end) {
            sl = csrc[e];
            float4 s4 = *(const float4*)(a_s + (size_t)sl * 4);
            x0 = expf(lrelu(s4.x + ad4.x) - m0);
            x1 = expf(lrelu(s4.y + ad4.y) - m1);
            x2 = expf(lrelu(s4.z + ad4.z) - m2);
            x3 = expf(lrelu(s4.w + ad4.w) - m3);
        }
        int cnt = min(32, end - c0);
        for (int i = 0; i < cnt; i++) {
            int s   = __shfl_sync(0xffffffffu, sl, i);
            float e0 = __shfl_sync(0xffffffffu, x0, i);
            float e1 = __shfl_sync(0xffffffffu, x1, i);
            float e2 = __shfl_sync(0xffffffffu, x2, i);
            float e3 = __shfl_sync(0xffffffffu, x3, i);
            den0 += e0; den1 += e1; den2 += e2; den3 += e3;
            const float* hp = h + (size_t)s * HF;
            acc[0] += e0 * hp[lane];        acc[1] += e0 * hp[32 + lane];
            acc[2] += e1 * hp[64 + lane];   acc[3] += e1 * hp[96 + lane];
            acc[4] += e2 * hp[128 + lane];  acc[5] += e2 * hp[160 + lane];
            acc[6] += e3 * hp[192 + lane];  acc[7] += e3 * hp[224 + lane];
        }
    }
    float den[4] = {den0, den1, den2, den3};
    float* op = outx + (size_t)d * HF;
#pragma unroll
    for (int j = 0; j < 8; j++) {
        int c = j * 32 + lane;
        op[c] = elu(acc[j] / den[j >> 1] + gb[c]);
    }
}

__global__ void bnapply_kernel(const float* __restrict__ z, const float* __restrict__ g,
                               const float* __restrict__ beta, float* __restrict__ acc,
                               const float* __restrict__ mu, const float* __restrict__ rstd) {
    int idx = blockIdx.x * blockDim.x + threadIdx.x;
    if (idx >= NN * FF) return;
    int f = idx & 63;
    acc[idx] += (z[idx] - mu[f]) * rstd[f] * g[f] + beta[f];
}

// ---------------- pooling + FC head ----------------
__global__ void pool_kernel(const float* __restrict__ acc, const int* __restrict__ batch,
                            float* __restrict__ pooled) {
    int idx = blockIdx.x * blockDim.x + threadIdx.x;
    if (idx >= NN * FF) return;
    int n = idx >> 6, f = idx & 63;
    atomicAdd(&pooled[batch[n] * FF + f], acc[idx]);
}

__global__ void fcbn_kernel(const float* __restrict__ A, const float* __restrict__ W,
                            const float* __restrict__ b, const float* __restrict__ g,
                            const float* __restrict__ beta, float* __restrict__ out,
                            int K, int Nc, int do_relu) {
    int j = blockIdx.x;
    int r = threadIdx.x;
    float y = b[j];
    for (int k = 0; k < K; k++) y += A[r * K + k] * W[k * Nc + j];
    __shared__ float sh[GG];
    __shared__ float s_mu, s_var;
    sh[r] = y;
    __syncthreads();
    if (r == 0) {
        float s = 0.f;
        for (int i = 0; i < GG; i++) s += sh[i];
        float mu = s / GG;
        float q = 0.f;
        for (int i = 0; i < GG; i++) { float dd = sh[i] - mu; q += dd * dd; }
        s_mu = mu; s_var = q / GG;
    }
    __syncthreads();
    float o = (y - s_mu) * rsqrtf(s_var + BNEPS) * g[j] + beta[j];
    if (do_relu) o = fmaxf(o, 0.f);
    out[r * Nc + j] = o;
}

// ---------------- launch ----------------
static inline void* sym(const void* s) {
    void* p = nullptr;
    cudaGetSymbolAddress(&p, s);
    return p;
}

extern "C" void kernel_launch(void* const* d_in, const int* in_sizes, int n_in,
                              void* d_out, int out_size) {
    const float* x       = (const float*)d_in[0];
    const int*  eidx     = (const int*)d_in[1];
    const int*  batch    = (const int*)d_in[2];
    const int*  sidx     = (const int*)d_in[3];
    const float* sattr   = (const float*)d_in[4];
    const float* gat_W   = (const float*)d_in[5];
    const float* gat_as  = (const float*)d_in[6];
    const float* gat_ad  = (const float*)d_in[7];
    const float* gat_b   = (const float*)d_in[8];
    const float* mlp_W   = (const float*)d_in[9];
    const float* mlp_b   = (const float*)d_in[10];
    const float* mlp_g   = (const float*)d_in[11];
    const float* mlp_be  = (const float*)d_in[12];
    const float* fc1_W   = (const float*)d_in[13];
    const float* fc1_b   = (const float*)d_in[14];
    const float* fc1_g   = (const float*)d_in[15];
    const float* fc1_be  = (const float*)d_in[16];
    const float* fc2_W   = (const float*)d_in[17];
    const float* fc2_b   = (const float*)d_in[18];
    const float* fc2_g   = (const float*)d_in[19];
    const float* fc2_be  = (const float*)d_in[20];
    const float* fc3_W   = (const float*)d_in[21];
    const float* fc3_b   = (const float*)d_in[22];
    const float* fc3_g   = (const float*)d_in[23];
    const float* fc3_be  = (const float*)d_in[24];
    float* out = (float*)d_out;

    float* p_xs     = (float*)sym(d_xs);
    float* p_xh     = (float*)sym(d_xh);
    float* p_h      = (float*)sym(d_h);
    float* p_as     = (float*)sym(d_as);
    float* p_ad     = (float*)sym(d_ad);
    float* p_gacc   = (float*)sym(d_gacc);
    float* p_z      = (float*)sym(d_z);
    float* p_acc    = (float*)sym(d_acc);
    float* p_bnpart = (float*)sym(d_bnpart);
    float* p_bnmu   = (float*)sym(d_bnmu);
    float* p_bnrstd = (float*)sym(d_bnrstd);
    float* p_pooled = (float*)sym(d_pooled);
    float* p_h1     = (float*)sym(d_h1);
    float* p_h2     = (float*)sym(d_h2);
    int*   p_cnt    = (int*)sym(d_cnt);
    int*   p_rowptr = (int*)sym(d_rowptr);
    int*   p_csrc   = (int*)sym(d_csrc);
    float* p_cattr  = (float*)sym(d_cattr);

    const int TB = 256;
    const int EB = (ESZ + TB - 1) / TB;
    const int NW = (NN * 32 + TB - 1) / TB;   // warp-per-node grids

    // ---- batched CSR build (5 graphs) ----
    zero_i_kernel<<<(10 * NN + TB - 1) / TB, TB>>>(p_cnt, 10 * NN);
    hist5_kernel<<<dim3(EB, 5), TB>>>(sidx, eidx, p_cnt);
    scan5_kernel<<<5, 1024>>>(p_cnt, p_rowptr);
    fill5_kernel<<<dim3(EB, 5), TB>>>(sidx, eidx, sattr, p_rowptr, p_cnt, p_csrc, p_cattr);

    // ---- solo passes (gather form) ----
    gatherA_kernel<<<dim3(NW, 4), TB>>>(p_rowptr, p_csrc, p_cattr, x, p_xs, p_xh);
    gather3_kernel<<<NW, TB>>>(p_rowptr, p_csrc, p_cattr,
                               p_xh, p_xh + (size_t)NN * FF, p_xh + (size_t)2 * NN * FF,
                               p_xs + (size_t)NN * FF, p_xs + (size_t)2 * NN * FF,
                               p_xs + (size_t)3 * NN * FF);

    // ---- residual accumulator = x ----
    copy_kernel<<<(NN * FF / 4 + TB - 1) / TB, TB>>>((const float4*)x, (float4*)p_acc, NN * FF / 4);

    // ---- 4 GAT + MLP + BN layers ----
    const int* gat_rp = p_rowptr + (size_t)4 * (NN + 1);
    const int* gat_cs = p_csrc + (size_t)4 * ESZ;
    for (int i = 0; i < 4; i++) {
        gemm_asad_kernel<<<(NN / 64) * (HF / 64), TB>>>(p_xs + (size_t)i * NN * FF,
                                                        gat_W + (size_t)i * FF * HF, p_h,
                                                        gat_as + (size_t)i * HH * FF,
                                                        gat_ad + (size_t)i * HH * FF,
                                                        p_as, p_ad);
        gat_agg_kernel<<<NW, TB>>>(gat_rp, gat_cs, p_as, p_ad, p_h,
                                   gat_b + (size_t)i * HF, p_gacc);
        gemm_bn_kernel<<<NN / 64, TB>>>(p_gacc, mlp_W + (size_t)i * HF * FF,
                                        mlp_b + (size_t)i * FF, p_z, p_bnpart);
        bnstat2_kernel<<<1, 256>>>(p_bnpart, p_bnmu, p_bnrstd);
        bnapply_kernel<<<(NN * FF + TB - 1) / TB, TB>>>(p_z, mlp_g + (size_t)i * FF,
                                                        mlp_be + (size_t)i * FF,
                                                        p_acc, p_bnmu, p_bnrstd);
    }

    // ---- pooling + FC head ----
    zero_f_kernel<<<(GG * FF / 4 + TB - 1) / TB, TB>>>((float4*)p_pooled, GG * FF / 4);
    pool_kernel<<<(NN * FF + TB - 1) / TB, TB>>>(p_acc, batch, p_pooled);
    fcbn_kernel<<<256, GG>>>(p_pooled, fc1_W, fc1_b, fc1_g, fc1_be, p_h1, 64, 256, 1);
    fcbn_kernel<<<128, GG>>>(p_h1, fc2_W, fc2_b, fc2_g, fc2_be, p_h2, 256, 128, 1);
    fcbn_kernel<<<NCLS, GG>>>(p_h2, fc3_W, fc3_b, fc3_g, fc3_be, out, 128, NCLS, 0);
}

// round 7
// speedup vs baseline: 2.0692x; 1.3356x over previous
#include <cuda_runtime.h>
#include <math.h>

#define NN   32768
#define FF   64
#define HH   4
#define HF   256
#define ESZ  524288
#define EGZ  524288
#define GG   64
#define NCLS 10
#define BNEPS 1e-5f

// ---------------- device scratch (static allocation only) ----------------
__device__ float  d_xs[4][NN*FF];      // x0..x3 (GAT inputs)
__device__ float  d_xh[3][NN*FF];      // xh1..xh3 intermediates
__device__ float  d_h[4][NN*HF];       // h_i = xs_i @ W_i
__device__ float  d_as[4][NN*HH];
__device__ float  d_ad[4][NN*HH];
__device__ float  d_gacc[4][NN*HF];    // elu(gat output) per layer
__device__ float  d_z[4][NN*FF];       // mlp output per layer
__device__ float  d_bnpart[4*256*FF*2];
__device__ float  d_bnmu[4][FF];
__device__ float  d_bnrstd[4][FF];
__device__ float  d_pooled[GG*FF];
__device__ float  d_h1[GG*256];
__device__ float  d_h2[GG*128];
// CSR scratch: graphs 0..3 = scatter graphs (packed src+attr), 4 = gat edges
__device__ int    d_cnt[5][2*NN];      // per graph: [0,NN)=hist, [NN,2NN)=cursor
__device__ int    d_rowptr[5][NN+1];
__device__ int2   d_cedge[4][ESZ];     // (src, attr bits)
__device__ int    d_csrc4[ESZ];        // gat graph src

// ---------------- helpers ----------------
__device__ __forceinline__ float lrelu(float x) { return x >= 0.f ? x : 0.2f * x; }
__device__ __forceinline__ float elu(float x)   { return x > 0.f ? x : expm1f(x); }

__global__ void zero_i_kernel(int* p, int n) {
    int i = blockIdx.x * blockDim.x + threadIdx.x;
    if (i < n) p[i] = 0;
}
__global__ void zero_f_kernel(float4* p, int n4) {
    int i = blockIdx.x * blockDim.x + threadIdx.x;
    if (i < n4) p[i] = make_float4(0.f, 0.f, 0.f, 0.f);
}

// ---------------- batched CSR build (5 graphs at once) ----------------
__global__ void hist5_kernel(const int* __restrict__ sidx, const int* __restrict__ eidx,
                             int* __restrict__ cnt) {
    int g = blockIdx.y;
    const int* dst = (g < 4) ? (sidx + (size_t)g * 2 * ESZ + ESZ) : (eidx + EGZ);
    int e = blockIdx.x * blockDim.x + threadIdx.x;
    if (e < ESZ) atomicAdd(&cnt[(size_t)g * 2 * NN + dst[e]], 1);
}

__global__ void scan5_kernel(const int* __restrict__ cnt_all, int* __restrict__ rowptr_all) {
    int g = blockIdx.x;
    const int* cnt = cnt_all + (size_t)g * 2 * NN;
    int* rowptr = rowptr_all + (size_t)g * (NN + 1);
    __shared__ int sh[1024];
    int t = threadIdx.x;
    int base = t * 32;
    int local[32];
    int s = 0;
#pragma unroll
    for (int i = 0; i < 32; i++) { local[i] = s; s += cnt[base + i]; }
    sh[t] = s;
    __syncthreads();
    for (int o = 1; o < 1024; o <<= 1) {
        int v = (t >= o) ? sh[t - o] : 0;
        __syncthreads();
        sh[t] += v;
        __syncthreads();
    }
    int off = (t == 0) ? 0 : sh[t - 1];
#pragma unroll
    for (int i = 0; i < 32; i++) rowptr[base + i] = off + local[i];
    if (t == 1023) rowptr[NN] = sh[1023];
}

__global__ void fill5_kernel(const int* __restrict__ sidx, const int* __restrict__ eidx,
                             const float* __restrict__ sattr,
                             const int* __restrict__ rowptr_all, int* __restrict__ cnt_all,
                             int2* __restrict__ cedge_all, int* __restrict__ csrc4) {
    int g = blockIdx.y;
    int e = blockIdx.x * blockDim.x + threadIdx.x;
    if (e >= ESZ) return;
    const int* rowptr = rowptr_all + (size_t)g * (NN + 1);
    int* cursor = cnt_all + (size_t)g * 2 * NN + NN;
    if (g < 4) {
        const int* src = sidx + (size_t)g * 2 * ESZ;
        const int* dst = src + ESZ;
        const float* attr = sattr + (size_t)g * ESZ;
        int d = dst[e];
        int pos = rowptr[d] + atomicAdd(&cursor[d], 1);
        cedge_all[(size_t)g * ESZ + pos] = make_int2(src[e], __float_as_int(attr[e]));
    } else {
        int d = eidx[EGZ + e];
        int pos = rowptr[d] + atomicAdd(&cursor[d], 1);
        csrc4[pos] = eidx[e];
    }
}

// ---------------- CSR gathers (warp per node) ----------------
// grid.y = 4: g=0 -> xs0 (no abs), g=1..3 -> xh[g-1] (abs)
__global__ void gatherA_kernel(const int* __restrict__ rowptr_all, const int2* __restrict__ cedge_all,
                               const float* __restrict__ in,
                               float* __restrict__ xs0, float* __restrict__ xh_base) {
    int g = blockIdx.y;
    const int* rowptr = rowptr_all + (size_t)g * (NN + 1);
    const int2* ce = cedge_all + (size_t)g * ESZ;
    int warp = (blockIdx.x * blockDim.x + threadIdx.x) >> 5;
    int lane = threadIdx.x & 31;
    if (warp >= NN) return;
    int beg = rowptr[warp], end = rowptr[warp + 1];
    float a0 = 0.f, a1 = 0.f;
    for (int e = beg; e < end; e++) {
        int2 p = ce[e];
        float a = __int_as_float(p.y);
        const float* ip = in + (size_t)p.x * FF;
        a0 += a * ip[lane];
        a1 += a * ip[32 + lane];
    }
    float* out = (g == 0) ? xs0 : (xh_base + (size_t)(g - 1) * NN * FF);
    if (g > 0) { a0 = fabsf(a0); a1 = fabsf(a1); }
    float* op = out + (size_t)warp * FF;
    op[lane] = a0;
    op[32 + lane] = a1;
}

// three inputs through graph-0 CSR
__global__ void gather3_kernel(const int* __restrict__ rowptr, const int2* __restrict__ ce,
                               const float* __restrict__ in0, const float* __restrict__ in1,
                               const float* __restrict__ in2,
                               float* __restrict__ o0, float* __restrict__ o1,
                               float* __restrict__ o2) {
    int warp = (blockIdx.x * blockDim.x + threadIdx.x) >> 5;
    int lane = threadIdx.x & 31;
    if (warp >= NN) return;
    int beg = rowptr[warp], end = rowptr[warp + 1];
    float a00 = 0.f, a01 = 0.f, a10 = 0.f, a11 = 0.f, a20 = 0.f, a21 = 0.f;
    for (int e = beg; e < end; e++) {
        int2 p = ce[e];
        float a = __int_as_float(p.y);
        size_t r = (size_t)p.x * FF;
        a00 += a * in0[r + lane];  a01 += a * in0[r + 32 + lane];
        a10 += a * in1[r + lane];  a11 += a * in1[r + 32 + lane];
        a20 += a * in2[r + lane];  a21 += a * in2[r + 32 + lane];
    }
    size_t w = (size_t)warp * FF;
    o0[w + lane] = a00;  o0[w + 32 + lane] = a01;
    o1[w + lane] = a10;  o1[w + 32 + lane] = a11;
    o2[w + lane] = a20;  o2[w + 32 + lane] = a21;
}

// ---------------- GEMM 1 (batched over layers): h = xs@W, fused a_s/a_d ----------
// BM=128, BN=64(one head), BK=16, 256 threads, 8x4 per thread.
// grid.x = (NN/128)*4heads, grid.z = layer.
__global__ void gemm_asad_kernel(const float* __restrict__ xs_all, const float* __restrict__ W_all,
                                 float* __restrict__ h_all,
                                 const float* __restrict__ asrc_all, const float* __restrict__ adst_all,
                                 float* __restrict__ as_all, float* __restrict__ ad_all) {
    const int K = FF, Nc = HF;
    int layer = blockIdx.z;
    const float* A = xs_all + (size_t)layer * NN * FF;
    const float* B = W_all + (size_t)layer * FF * HF;
    float* C = h_all + (size_t)layer * NN * HF;
    const float* asrc = asrc_all + (size_t)layer * HH * FF;
    const float* adst = adst_all + (size_t)layer * HH * FF;
    float* a_s = as_all + (size_t)layer * NN * HH;
    float* a_d = ad_all + (size_t)layer * NN * HH;

    __shared__ float As[16][132];
    __shared__ float Bs[16][68];
    __shared__ float shs[128][17];
    __shared__ float shd[128][17];
    int tid = threadIdx.x;
    int tx = tid & 15, ty = tid >> 4;
    int hh = blockIdx.x & 3;
    int bm = (blockIdx.x >> 2) * 128;
    int bn = hh * 64;
    float acc[8][4] = {};
    for (int k0 = 0; k0 < K; k0 += 16) {
        {
            int kk = (tid & 3) * 4;
#pragma unroll
            for (int p = 0; p < 2; p++) {
                int m = (tid >> 2) + p * 64;
                float4 v = *(const float4*)(A + (size_t)(bm + m) * K + k0 + kk);
                As[kk + 0][m] = v.x; As[kk + 1][m] = v.y; As[kk + 2][m] = v.z; As[kk + 3][m] = v.w;
            }
        }
        {
            int kk = tid >> 4;
            int n = (tid & 15) * 4;
            *(float4*)&Bs[kk][n] = *(const float4*)(B + (size_t)(k0 + kk) * Nc + bn + n);
        }
        __syncthreads();
#pragma unroll
        for (int kk = 0; kk < 16; kk++) {
            float4 a0 = *(float4*)&As[kk][ty * 8];
            float4 a1 = *(float4*)&As[kk][ty * 8 + 4];
            float4 b  = *(float4*)&Bs[kk][tx * 4];
            float ar[8] = {a0.x, a0.y, a0.z, a0.w, a1.x, a1.y, a1.z, a1.w};
#pragma unroll
            for (int i = 0; i < 8; i++) {
                acc[i][0] += ar[i] * b.x;
                acc[i][1] += ar[i] * b.y;
                acc[i][2] += ar[i] * b.z;
                acc[i][3] += ar[i] * b.w;
            }
        }
        __syncthreads();
    }
    // store C (float4)
#pragma unroll
    for (int i = 0; i < 8; i++) {
        *(float4*)(C + (size_t)(bm + ty * 8 + i) * Nc + bn + tx * 4) =
            make_float4(acc[i][0], acc[i][1], acc[i][2], acc[i][3]);
    }
    // fused head-dot
    float ws[4], wd[4];
#pragma unroll
    for (int j = 0; j < 4; j++) {
        ws[j] = asrc[hh * 64 + tx * 4 + j];
        wd[j] = adst[hh * 64 + tx * 4 + j];
    }
#pragma unroll
    for (int i = 0; i < 8; i++) {
        float ps = acc[i][0] * ws[0] + acc[i][1] * ws[1] + acc[i][2] * ws[2] + acc[i][3] * ws[3];
        float pd = acc[i][0] * wd[0] + acc[i][1] * wd[1] + acc[i][2] * wd[2] + acc[i][3] * wd[3];
        shs[ty * 8 + i][tx] = ps;
        shd[ty * 8 + i][tx] = pd;
    }
    __syncthreads();
    if (tid < 128) {
        float s = 0.f, dd = 0.f;
#pragma unroll
        for (int t = 0; t < 16; t++) { s += shs[tid][t]; dd += shd[tid][t]; }
        a_s[(size_t)(bm + tid) * 4 + hh] = s;
        a_d[(size_t)(bm + tid) * 4 + hh] = dd;
    }
}

// ---------------- GEMM 2 (batched): z = gacc@W + b, fused BN partials ----------
// BM=128, Nc=64, K=256. grid.x = NN/128, grid.z = layer.
__global__ void gemm_bn_kernel(const float* __restrict__ gacc_all, const float* __restrict__ W_all,
                               const float* __restrict__ bias_all, float* __restrict__ z_all,
                               float* __restrict__ part) {
    const int K = HF, Nc = FF;
    int layer = blockIdx.z;
    const float* A = gacc_all + (size_t)layer * NN * HF;
    const float* B = W_all + (size_t)layer * HF * FF;
    const float* bias = bias_all + (size_t)layer * FF;
    float* C = z_all + (size_t)layer * NN * FF;

    __shared__ float As[16][132];
    __shared__ float Bs[16][68];
    __shared__ float shs[64][17];
    __shared__ float shq[64][17];
    int tid = threadIdx.x;
    int tx = tid & 15, ty = tid >> 4;
    int bm = blockIdx.x * 128;
    float acc[8][4] = {};
    for (int k0 = 0; k0 < K; k0 += 16) {
        {
            int kk = (tid & 3) * 4;
#pragma unroll
            for (int p = 0; p < 2; p++) {
                int m = (tid >> 2) + p * 64;
                float4 v = *(const float4*)(A + (size_t)(bm + m) * K + k0 + kk);
                As[kk + 0][m] = v.x; As[kk + 1][m] = v.y; As[kk + 2][m] = v.z; As[kk + 3][m] = v.w;
            }
        }
        {
            int kk = tid >> 4;
            int n = (tid & 15) * 4;
            *(float4*)&Bs[kk][n] = *(const float4*)(B + (size_t)(k0 + kk) * Nc + n);
        }
        __syncthreads();
#pragma unroll
        for (int kk = 0; kk < 16; kk++) {
            float4 a0 = *(float4*)&As[kk][ty * 8];
            float4 a1 = *(float4*)&As[kk][ty * 8 + 4];
            float4 b  = *(float4*)&Bs[kk][tx * 4];
            float ar[8] = {a0.x, a0.y, a0.z, a0.w, a1.x, a1.y, a1.z, a1.w};
#pragma unroll
            for (int i = 0; i < 8; i++) {
                acc[i][0] += ar[i] * b.x;
                acc[i][1] += ar[i] * b.y;
                acc[i][2] += ar[i] * b.z;
                acc[i][3] += ar[i] * b.w;
            }
        }
        __syncthreads();
    }
    float bs[4];
#pragma unroll
    for (int j = 0; j < 4; j++) bs[j] = bias[tx * 4 + j];
    float colsum[4] = {}, colsq[4] = {};
#pragma unroll
    for (int i = 0; i < 8; i++) {
        float v0 = acc[i][0] + bs[0];
        float v1 = acc[i][1] + bs[1];
        float v2 = acc[i][2] + bs[2];
        float v3 = acc[i][3] + bs[3];
        *(float4*)(C + (size_t)(bm + ty * 8 + i) * Nc + tx * 4) = make_float4(v0, v1, v2, v3);
        colsum[0] += v0; colsq[0] += v0 * v0;
        colsum[1] += v1; colsq[1] += v1 * v1;
        colsum[2] += v2; colsq[2] += v2 * v2;
        colsum[3] += v3; colsq[3] += v3 * v3;
    }
#pragma unroll
    for (int j = 0; j < 4; j++) {
        shs[tx * 4 + j][ty] = colsum[j];
        shq[tx * 4 + j][ty] = colsq[j];
    }
    __syncthreads();
    if (tid < 64) {
        float s = 0.f, q = 0.f;
#pragma unroll
        for (int t = 0; t < 16; t++) { s += shs[tid][t]; q += shq[tid][t]; }
        size_t pi = ((size_t)layer * 256 + blockIdx.x) * 64 + tid;
        part[pi * 2 + 0] = s;
        part[pi * 2 + 1] = q;
    }
}

// reduce 256 block partials per layer -> mu, rstd. grid.x = layer.
__global__ void bnstat2_kernel(const float* __restrict__ part,
                               float* __restrict__ mu_all, float* __restrict__ rstd_all) {
    int layer = blockIdx.x;
    int t = threadIdx.x;
    int c = t & 63;
    int cg = t >> 6;            // 4 chunks of 64 blocks
    double s = 0.0, q = 0.0;
    for (int b = cg * 64; b < (cg + 1) * 64; b++) {
        size_t pi = ((size_t)layer * 256 + b) * 64 + c;
        s += part[pi * 2 + 0];
        q += part[pi * 2 + 1];
    }
    __shared__ double shs[256], shq[256];
    shs[t] = s; shq[t] = q;
    __syncthreads();
    if (cg == 0) {
        s = shs[c] + shs[64 + c] + shs[128 + c] + shs[192 + c];
        q = shq[c] + shq[64 + c] + shq[128 + c] + shq[192 + c];
        double mu = s / NN;
        double var = q / NN - mu * mu;
        mu_all[(size_t)layer * FF + c] = (float)mu;
        rstd_all[(size_t)layer * FF + c] = rsqrtf((float)var + BNEPS);
    }
}

// ---------------- GAT aggregation (warp per node, one layer) ----------------
__global__ void gat_agg_kernel(const int* __restrict__ rowptr, const int* __restrict__ csrc,
                               const float* __restrict__ a_s, const float* __restrict__ a_d,
                               const float* __restrict__ h, const float* __restrict__ gb,
                               float* __restrict__ outx) {
    int warp = (blockIdx.x * blockDim.x + threadIdx.x) >> 5;
    int lane = threadIdx.x & 31;
    if (warp >= NN) return;
    int d = warp;
    int beg = rowptr[d], end = rowptr[d + 1];
    float4 ad4 = *(const float4*)(a_d + (size_t)d * 4);
    float4 sf4 = *(const float4*)(a_s + (size_t)d * 4);
    float sl0 = lrelu(sf4.x + ad4.x);
    float sl1 = lrelu(sf4.y + ad4.y);
    float sl2 = lrelu(sf4.z + ad4.z);
    float sl3 = lrelu(sf4.w + ad4.w);
    float m0 = sl0, m1 = sl1, m2 = sl2, m3 = sl3;
    for (int e = beg + lane; e < end; e += 32) {
        int s = csrc[e];
        float4 s4 = *(const float4*)(a_s + (size_t)s * 4);
        m0 = fmaxf(m0, lrelu(s4.x + ad4.x));
        m1 = fmaxf(m1, lrelu(s4.y + ad4.y));
        m2 = fmaxf(m2, lrelu(s4.z + ad4.z));
        m3 = fmaxf(m3, lrelu(s4.w + ad4.w));
    }
    for (int o = 16; o; o >>= 1) {
        m0 = fmaxf(m0, __shfl_xor_sync(0xffffffffu, m0, o));
        m1 = fmaxf(m1, __shfl_xor_sync(0xffffffffu, m1, o));
        m2 = fmaxf(m2, __shfl_xor_sync(0xffffffffu, m2, o));
        m3 = fmaxf(m3, __shfl_xor_sync(0xffffffffu, m3, o));
    }
    float acc[8];
    float den0, den1, den2, den3;
    {
        float e0 = expf(sl0 - m0), e1 = expf(sl1 - m1);
        float e2 = expf(sl2 - m2), e3 = expf(sl3 - m3);
        den0 = e0; den1 = e1; den2 = e2; den3 = e3;
        const float* hp = h + (size_t)d * HF;
        acc[0] = e0 * hp[lane];        acc[1] = e0 * hp[32 + lane];
        acc[2] = e1 * hp[64 + lane];   acc[3] = e1 * hp[96 + lane];
        acc[4] = e2 * hp[128 + lane];  acc[5] = e2 * hp[160 + lane];
        acc[6] = e3 * hp[192 + lane];  acc[7] = e3 * hp[224 + lane];
    }
    for (int c0 = beg; c0 < end; c0 += 32) {
        int e = c0 + lane;
        int sl = 0;
        float x0 = 0.f, x1 = 0.f, x2 = 0.f, x3 = 0.f;
        if (e < end) {
            sl = csrc[e];
            float4 s4 = *(const float4*)(a_s + (size_t)sl * 4);
            x0 = expf(lrelu(s4.x + ad4.x) - m0);
            x1 = expf(lrelu(s4.y + ad4.y) - m1);
            x2 = expf(lrelu(s4.z + ad4.z) - m2);
            x3 = expf(lrelu(s4.w + ad4.w) - m3);
        }
        int cnt = min(32, end - c0);
        for (int i = 0; i < cnt; i++) {
            int s   = __shfl_sync(0xffffffffu, sl, i);
            float e0 = __shfl_sync(0xffffffffu, x0, i);
            float e1 = __shfl_sync(0xffffffffu, x1, i);
            float e2 = __shfl_sync(0xffffffffu, x2, i);
            float e3 = __shfl_sync(0xffffffffu, x3, i);
            den0 += e0; den1 += e1; den2 += e2; den3 += e3;
            const float* hp = h + (size_t)s * HF;
            acc[0] += e0 * hp[lane];        acc[1] += e0 * hp[32 + lane];
            acc[2] += e1 * hp[64 + lane];   acc[3] += e1 * hp[96 + lane];
            acc[4] += e2 * hp[128 + lane];  acc[5] += e2 * hp[160 + lane];
            acc[6] += e3 * hp[192 + lane];  acc[7] += e3 * hp[224 + lane];
        }
    }
    float den[4] = {den0, den1, den2, den3};
    float* op = outx + (size_t)d * HF;
#pragma unroll
    for (int j = 0; j < 8; j++) {
        int c = j * 32 + lane;
        op[c] = elu(acc[j] / den[j >> 1] + gb[c]);
    }
}

// ---------------- fused BN apply + residual + pool ----------------
__global__ void bnpool_kernel(const float* __restrict__ x, const float* __restrict__ z_all,
                              const float* __restrict__ g_all, const float* __restrict__ beta_all,
                              const float* __restrict__ mu_all, const float* __restrict__ rstd_all,
                              const int* __restrict__ batch, float* __restrict__ pooled) {
    int idx = blockIdx.x * blockDim.x + threadIdx.x;
    if (idx >= NN * FF) return;
    int n = idx >> 6, f = idx & 63;
    float v = x[idx];
#pragma unroll
    for (int i = 0; i < 4; i++) {
        float zz = z_all[(size_t)i * NN * FF + idx];
        v += (zz - mu_all[i * FF + f]) * rstd_all[i * FF + f] * g_all[i * FF + f]
             + beta_all[i * FF + f];
    }
    atomicAdd(&pooled[batch[n] * FF + f], v);
}

// ---------------- tiny FC + BN head ----------------
__global__ void fcbn_kernel(const float* __restrict__ A, const float* __restrict__ W,
                            const float* __restrict__ b, const float* __restrict__ g,
                            const float* __restrict__ beta, float* __restrict__ out,
                            int K, int Nc, int do_relu) {
    int j = blockIdx.x;
    int r = threadIdx.x;
    float y = b[j];
    for (int k = 0; k < K; k++) y += A[r * K + k] * W[k * Nc + j];
    __shared__ float sh[GG];
    __shared__ float s_mu, s_var;
    sh[r] = y;
    __syncthreads();
    if (r == 0) {
        float s = 0.f;
        for (int i = 0; i < GG; i++) s += sh[i];
        float mu = s / GG;
        float q = 0.f;
        for (int i = 0; i < GG; i++) { float dd = sh[i] - mu; q += dd * dd; }
        s_mu = mu; s_var = q / GG;
    }
    __syncthreads();
    float o = (y - s_mu) * rsqrtf(s_var + BNEPS) * g[j] + beta[j];
    if (do_relu) o = fmaxf(o, 0.f);
    out[r * Nc + j] = o;
}

// ---------------- launch ----------------
static inline void* sym(const void* s) {
    void* p = nullptr;
    cudaGetSymbolAddress(&p, s);
    return p;
}

extern "C" void kernel_launch(void* const* d_in, const int* in_sizes, int n_in,
                              void* d_out, int out_size) {
    const float* x       = (const float*)d_in[0];
    const int*  eidx     = (const int*)d_in[1];
    const int*  batch    = (const int*)d_in[2];
    const int*  sidx     = (const int*)d_in[3];
    const float* sattr   = (const float*)d_in[4];
    const float* gat_W   = (const float*)d_in[5];
    const float* gat_as  = (const float*)d_in[6];
    const float* gat_ad  = (const float*)d_in[7];
    const float* gat_b   = (const float*)d_in[8];
    const float* mlp_W   = (const float*)d_in[9];
    const float* mlp_b   = (const float*)d_in[10];
    const float* mlp_g   = (const float*)d_in[11];
    const float* mlp_be  = (const float*)d_in[12];
    const float* fc1_W   = (const float*)d_in[13];
    const float* fc1_b   = (const float*)d_in[14];
    const float* fc1_g   = (const float*)d_in[15];
    const float* fc1_be  = (const float*)d_in[16];
    const float* fc2_W   = (const float*)d_in[17];
    const float* fc2_b   = (const float*)d_in[18];
    const float* fc2_g   = (const float*)d_in[19];
    const float* fc2_be  = (const float*)d_in[20];
    const float* fc3_W   = (const float*)d_in[21];
    const float* fc3_b   = (const float*)d_in[22];
    const float* fc3_g   = (const float*)d_in[23];
    const float* fc3_be  = (const float*)d_in[24];
    float* out = (float*)d_out;

    float* p_xs     = (float*)sym(d_xs);
    float* p_xh     = (float*)sym(d_xh);
    float* p_h      = (float*)sym(d_h);
    float* p_as     = (float*)sym(d_as);
    float* p_ad     = (float*)sym(d_ad);
    float* p_gacc   = (float*)sym(d_gacc);
    float* p_z      = (float*)sym(d_z);
    float* p_bnpart = (float*)sym(d_bnpart);
    float* p_bnmu   = (float*)sym(d_bnmu);
    float* p_bnrstd = (float*)sym(d_bnrstd);
    float* p_pooled = (float*)sym(d_pooled);
    float* p_h1     = (float*)sym(d_h1);
    float* p_h2     = (float*)sym(d_h2);
    int*   p_cnt    = (int*)sym(d_cnt);
    int*   p_rowptr = (int*)sym(d_rowptr);
    int2*  p_cedge  = (int2*)sym(d_cedge);
    int*   p_csrc4  = (int*)sym(d_csrc4);

    const int TB = 256;
    const int EB = (ESZ + TB - 1) / TB;
    const int NW = (NN * 32 + TB - 1) / TB;   // warp-per-node grids

    // ---- batched CSR build (5 graphs) ----
    zero_i_kernel<<<(10 * NN + TB - 1) / TB, TB>>>(p_cnt, 10 * NN);
    hist5_kernel<<<dim3(EB, 5), TB>>>(sidx, eidx, p_cnt);
    scan5_kernel<<<5, 1024>>>(p_cnt, p_rowptr);
    fill5_kernel<<<dim3(EB, 5), TB>>>(sidx, eidx, sattr, p_rowptr, p_cnt, p_cedge, p_csrc4);

    // ---- solo passes (gather form) ----
    gatherA_kernel<<<dim3(NW, 4), TB>>>(p_rowptr, p_cedge, x, p_xs, p_xh);
    gather3_kernel<<<NW, TB>>>(p_rowptr, p_cedge,
                               p_xh, p_xh + (size_t)NN * FF, p_xh + (size_t)2 * NN * FF,
                               p_xs + (size_t)NN * FF, p_xs + (size_t)2 * NN * FF,
                               p_xs + (size_t)3 * NN * FF);

    // ---- batched GEMM1 + fused a_s/a_d (all 4 layers) ----
    gemm_asad_kernel<<<dim3((NN / 128) * 4, 1, 4), TB>>>(p_xs, gat_W, p_h, gat_as, gat_ad,
                                                         p_as, p_ad);

    // ---- GAT aggregation per layer (keeps each h_i L2-resident) ----
    const int* gat_rp = p_rowptr + (size_t)4 * (NN + 1);
    for (int i = 0; i < 4; i++) {
        gat_agg_kernel<<<NW, TB>>>(gat_rp, p_csrc4,
                                   p_as + (size_t)i * NN * HH, p_ad + (size_t)i * NN * HH,
                                   p_h + (size_t)i * NN * HF, gat_b + (size_t)i * HF,
                                   p_gacc + (size_t)i * NN * HF);
    }

    // ---- batched GEMM2 + fused BN partials ----
    gemm_bn_kernel<<<dim3(NN / 128, 1, 4), TB>>>(p_gacc, mlp_W, mlp_b, p_z, p_bnpart);
    bnstat2_kernel<<<4, 256>>>(p_bnpart, p_bnmu, p_bnrstd);

    // ---- fused BN apply + residual + pool ----
    zero_f_kernel<<<(GG * FF / 4 + TB - 1) / TB, TB>>>((float4*)p_pooled, GG * FF / 4);
    bnpool_kernel<<<(NN * FF + TB - 1) / TB, TB>>>(x, p_z, mlp_g, mlp_be, p_bnmu, p_bnrstd,
                                                   batch, p_pooled);

    // ---- FC head ----
    fcbn_kernel<<<256, GG>>>(p_pooled, fc1_W, fc1_b, fc1_g, fc1_be, p_h1, 64, 256, 1);
    fcbn_kernel<<<128, GG>>>(p_h1, fc2_W, fc2_b, fc2_g, fc2_be, p_h2, 256, 128, 1);
    fcbn_kernel<<<NCLS, GG>>>(p_h2, fc3_W, fc3_b, fc3_g, fc3_be, out, 128, NCLS, 0);
}